// round 2
// baseline (speedup 1.0000x reference)
#include <cuda_runtime.h>
#include <cstdint>

#define N_NODES 100000
#define N_EDGES 1600000
#define IN_DIM  165
#define HIDDEN  128
#define OUT_DIM 2

// Scratch (static device globals — no runtime allocation allowed)
__device__ float g_h1[(size_t)N_NODES * HIDDEN];    // x @ W1
__device__ float g_agg1[(size_t)N_NODES * HIDDEN];  // aggregated layer-1
__device__ float g_h2[(size_t)N_NODES * OUT_DIM];   // relu(.)@W2
__device__ float g_dinv[N_NODES];
__device__ int   g_deg[N_NODES];

// ---------------------------------------------------------------------------
// degree / norm
// ---------------------------------------------------------------------------
__global__ void init_deg_kernel() {
    int i = blockIdx.x * blockDim.x + threadIdx.x;
    if (i < N_NODES) g_deg[i] = 1;  // self-loop
}

__global__ void hist_kernel(const int* __restrict__ dst) {
    int e = blockIdx.x * blockDim.x + threadIdx.x;
    if (e < N_EDGES) atomicAdd(&g_deg[dst[e]], 1);
}

__global__ void dinv_kernel() {
    int i = blockIdx.x * blockDim.x + threadIdx.x;
    if (i < N_NODES) g_dinv[i] = rsqrtf((float)g_deg[i]);
}

// ---------------------------------------------------------------------------
// GEMM1: h1[N,128] = x[N,165] @ W1[165,128]   (fp32 SIMT, 128x128 tile, 8x8/thr)
// ---------------------------------------------------------------------------
__global__ void gemm1_kernel(const float* __restrict__ X, const float* __restrict__ W) {
    __shared__ float As[8][132];   // [k][row], padded
    __shared__ float Bs[8][128];   // [k][col]
    const int row0 = blockIdx.x * 128;
    const int tid  = threadIdx.x;          // 0..255
    const int tr   = tid >> 4;             // 0..15
    const int tc   = tid & 15;             // 0..15

    float acc[8][8];
#pragma unroll
    for (int i = 0; i < 8; i++)
#pragma unroll
        for (int j = 0; j < 8; j++) acc[i][j] = 0.f;

    for (int k0 = 0; k0 < IN_DIM; k0 += 8) {
        // load A tile: 128 rows x 8 k
#pragma unroll
        for (int t = 0; t < 4; t++) {
            int i = tid + t * 256;
            int r = i >> 3, c = i & 7;
            int gr = row0 + r, gc = k0 + c;
            As[c][r] = (gr < N_NODES && gc < IN_DIM) ? X[(size_t)gr * IN_DIM + gc] : 0.f;
        }
        // load B tile: 8 k x 128 cols
#pragma unroll
        for (int t = 0; t < 4; t++) {
            int i = tid + t * 256;
            int r = i >> 7, c = i & 127;
            int gk = k0 + r;
            Bs[r][c] = (gk < IN_DIM) ? W[gk * HIDDEN + c] : 0.f;
        }
        __syncthreads();
#pragma unroll
        for (int k = 0; k < 8; k++) {
            float a[8], b[8];
#pragma unroll
            for (int i = 0; i < 8; i++) a[i] = As[k][tr * 8 + i];
#pragma unroll
            for (int j = 0; j < 8; j++) b[j] = Bs[k][tc * 8 + j];
#pragma unroll
            for (int i = 0; i < 8; i++)
#pragma unroll
                for (int j = 0; j < 8; j++) acc[i][j] = fmaf(a[i], b[j], acc[i][j]);
        }
        __syncthreads();
    }

#pragma unroll
    for (int i = 0; i < 8; i++) {
        int gr = row0 + tr * 8 + i;
        if (gr < N_NODES) {
            float* o = g_h1 + (size_t)gr * HIDDEN + tc * 8;
#pragma unroll
            for (int j = 0; j < 8; j += 4) {
                *(float4*)(o + j) = make_float4(acc[i][j], acc[i][j + 1],
                                                acc[i][j + 2], acc[i][j + 3]);
            }
        }
    }
}

// ---------------------------------------------------------------------------
// agg1 init: agg1[i] = dinv[i]^2 * h1[i]   (self-loop term)
// ---------------------------------------------------------------------------
__global__ void init_agg1_kernel() {
    int gtid = blockIdx.x * blockDim.x + threadIdx.x;
    if (gtid >= N_NODES * 32) return;
    int node = gtid >> 5, lane = gtid & 31;
    float di = g_dinv[node];
    float n = di * di;
    float4 v = ((const float4*)(g_h1 + (size_t)node * HIDDEN))[lane];
    v.x *= n; v.y *= n; v.z *= n; v.w *= n;
    ((float4*)(g_agg1 + (size_t)node * HIDDEN))[lane] = v;
}

// ---------------------------------------------------------------------------
// agg1: one warp per edge, 128 feats as 32 x float4, vector reduction to L2
// ---------------------------------------------------------------------------
__global__ void agg1_kernel(const int* __restrict__ src,
                            const int* __restrict__ dst) {
    long long gtid = (long long)blockIdx.x * blockDim.x + threadIdx.x;
    int e    = (int)(gtid >> 5);
    int lane = (int)(gtid & 31);
    if (e >= N_EDGES) return;
    int s = src[e], d = dst[e];
    float norm = g_dinv[s] * g_dinv[d];
    float4 v = ((const float4*)(g_h1 + (size_t)s * HIDDEN))[lane];
    float4* op = ((float4*)(g_agg1 + (size_t)d * HIDDEN)) + lane;
    asm volatile("red.global.add.v4.f32 [%0], {%1, %2, %3, %4};"
                 :: "l"(op), "f"(v.x * norm), "f"(v.y * norm),
                    "f"(v.z * norm), "f"(v.w * norm)
                 : "memory");
}

// ---------------------------------------------------------------------------
// layer2: h2 = relu(agg1 + b1) @ W2; also seed out with self-loop + b2
// one warp per node, each lane owns 4 features
// ---------------------------------------------------------------------------
__global__ void layer2_kernel(const float* __restrict__ b1,
                              const float* __restrict__ W2,
                              const float* __restrict__ b2,
                              float* __restrict__ out) {
    int gtid = blockIdx.x * blockDim.x + threadIdx.x;
    if (gtid >= N_NODES * 32) return;
    int node = gtid >> 5, lane = gtid & 31;
    float4 h  = ((const float4*)(g_agg1 + (size_t)node * HIDDEN))[lane];
    float4 bb = ((const float4*)b1)[lane];
    h.x = fmaxf(h.x + bb.x, 0.f);
    h.y = fmaxf(h.y + bb.y, 0.f);
    h.z = fmaxf(h.z + bb.z, 0.f);
    h.w = fmaxf(h.w + bb.w, 0.f);
    // W2 row-major [128][2]; lane's features 4lane..4lane+3 => 8 floats
    const float4* wv = (const float4*)W2;
    float4 wa = wv[2 * lane], wb = wv[2 * lane + 1];
    float o0 = h.x * wa.x + h.y * wa.z + h.z * wb.x + h.w * wb.z;
    float o1 = h.x * wa.y + h.y * wa.w + h.z * wb.y + h.w * wb.w;
#pragma unroll
    for (int off = 16; off; off >>= 1) {
        o0 += __shfl_xor_sync(0xffffffffu, o0, off);
        o1 += __shfl_xor_sync(0xffffffffu, o1, off);
    }
    if (lane == 0) {
        g_h2[2 * node]     = o0;
        g_h2[2 * node + 1] = o1;
        float di = g_dinv[node];
        float n  = di * di;
        out[2 * node]     = fmaf(o0, n, b2[0]);
        out[2 * node + 1] = fmaf(o1, n, b2[1]);
    }
}

// ---------------------------------------------------------------------------
// agg2: one thread per edge on 2-dim features, red.v2
// ---------------------------------------------------------------------------
__global__ void agg2_kernel(const int* __restrict__ src,
                            const int* __restrict__ dst,
                            float* __restrict__ out) {
    int e = blockIdx.x * blockDim.x + threadIdx.x;
    if (e >= N_EDGES) return;
    int s = src[e], d = dst[e];
    float norm = g_dinv[s] * g_dinv[d];
    float2 h = *(const float2*)(g_h2 + 2 * (size_t)s);
    asm volatile("red.global.add.v2.f32 [%0], {%1, %2};"
                 :: "l"(out + 2 * (size_t)d), "f"(h.x * norm), "f"(h.y * norm)
                 : "memory");
}

// ---------------------------------------------------------------------------
extern "C" void kernel_launch(void* const* d_in, const int* in_sizes, int n_in,
                              void* d_out, int out_size) {
    const float* x  = (const float*)d_in[0];
    const int*   ei = (const int*)d_in[1];
    const float* W1 = (const float*)d_in[2];
    const float* b1 = (const float*)d_in[3];
    const float* W2 = (const float*)d_in[4];
    const float* b2 = (const float*)d_in[5];
    float*       out = (float*)d_out;

    const int* src = ei;
    const int* dst = ei + N_EDGES;

    init_deg_kernel<<<(N_NODES + 255) / 256, 256>>>();
    hist_kernel<<<(N_EDGES + 255) / 256, 256>>>(dst);
    dinv_kernel<<<(N_NODES + 255) / 256, 256>>>();

    gemm1_kernel<<<(N_NODES + 127) / 128, 256>>>(x, W1);

    init_agg1_kernel<<<(N_NODES * 32 + 255) / 256, 256>>>();
    agg1_kernel<<<(int)(((long long)N_EDGES * 32 + 255) / 256), 256>>>(src, dst);

    layer2_kernel<<<(N_NODES * 32 + 255) / 256, 256>>>(b1, W2, b2, out);
    agg2_kernel<<<(N_EDGES + 255) / 256, 256>>>(src, dst, out);
}

// round 3
// speedup vs baseline: 1.2012x; 1.2012x over previous
#include <cuda_runtime.h>
#include <cstdint>

#define N_NODES 100000
#define N_EDGES 1600000
#define IN_DIM  165
#define HIDDEN  128
#define OUT_DIM 2

#define SCAN_BLOCK 512
#define NB_SCAN ((N_NODES + SCAN_BLOCK - 1) / SCAN_BLOCK)   // 196

// ---------------------------------------------------------------------------
// Static scratch
// ---------------------------------------------------------------------------
__device__ float g_h1[(size_t)N_NODES * HIDDEN];     // x @ W1
__device__ float g_agg1[(size_t)N_NODES * HIDDEN];   // aggregated layer-1
__device__ float g_h2[(size_t)N_NODES * OUT_DIM];    // relu(.) @ W2
__device__ float g_dinv[N_NODES];
__device__ int   g_cnt[N_NODES];                     // degree incl self-loop
__device__ int   g_rowstart[N_NODES + 1];
__device__ int   g_cursor[N_NODES];
__device__ int   g_bsum[NB_SCAN];
__device__ int   g_bsum_ex[NB_SCAN];
__device__ int   g_csr_src[N_EDGES + N_NODES];       // in-edges per node (incl self)

// ---------------------------------------------------------------------------
// degree / CSR build
// ---------------------------------------------------------------------------
__global__ void init_cnt_kernel() {
    int i = blockIdx.x * blockDim.x + threadIdx.x;
    if (i < N_NODES) g_cnt[i] = 1;   // self-loop
}

__global__ void hist_kernel(const int* __restrict__ dst) {
    int e = blockIdx.x * blockDim.x + threadIdx.x;
    if (e < N_EDGES) atomicAdd(&g_cnt[dst[e]], 1);
}

__global__ void dinv_kernel() {
    int i = blockIdx.x * blockDim.x + threadIdx.x;
    if (i < N_NODES) g_dinv[i] = rsqrtf((float)g_cnt[i]);
}

// block-wise exclusive scan of g_cnt -> g_rowstart (partial), block sums -> g_bsum
__global__ void scan1_kernel() {
    __shared__ int s0[SCAN_BLOCK], s1[SCAN_BLOCK];
    int t = threadIdx.x;
    int i = blockIdx.x * SCAN_BLOCK + t;
    int v = (i < N_NODES) ? g_cnt[i] : 0;
    int* a = s0; int* b = s1;
    a[t] = v;
    __syncthreads();
#pragma unroll
    for (int off = 1; off < SCAN_BLOCK; off <<= 1) {
        b[t] = (t >= off) ? a[t] + a[t - off] : a[t];
        __syncthreads();
        int* tmp = a; a = b; b = tmp;
    }
    if (i < N_NODES) g_rowstart[i] = a[t] - v;   // exclusive
    if (t == SCAN_BLOCK - 1) g_bsum[blockIdx.x] = a[t];
}

// exclusive scan of the block sums (single block)
__global__ void scan2_kernel() {
    __shared__ int s0[SCAN_BLOCK], s1[SCAN_BLOCK];
    int t = threadIdx.x;
    int v = (t < NB_SCAN) ? g_bsum[t] : 0;
    int* a = s0; int* b = s1;
    a[t] = v;
    __syncthreads();
#pragma unroll
    for (int off = 1; off < SCAN_BLOCK; off <<= 1) {
        b[t] = (t >= off) ? a[t] + a[t - off] : a[t];
        __syncthreads();
        int* tmp = a; a = b; b = tmp;
    }
    if (t < NB_SCAN) g_bsum_ex[t] = a[t] - v;
}

// add block offsets; init cursor; write rowstart[N]
__global__ void scan3_kernel() {
    int i = blockIdx.x * blockDim.x + threadIdx.x;
    if (i < N_NODES) {
        int r = g_rowstart[i] + g_bsum_ex[i / SCAN_BLOCK];
        g_rowstart[i] = r;
        g_cursor[i]   = r;
    } else if (i == N_NODES) {
        g_rowstart[N_NODES] = N_EDGES + N_NODES;
    }
}

__global__ void fill_self_kernel() {
    int i = blockIdx.x * blockDim.x + threadIdx.x;
    if (i < N_NODES) {
        int pos = atomicAdd(&g_cursor[i], 1);
        g_csr_src[pos] = i;
    }
}

__global__ void fill_edges_kernel(const int* __restrict__ src,
                                  const int* __restrict__ dst) {
    int e = blockIdx.x * blockDim.x + threadIdx.x;
    if (e < N_EDGES) {
        int d   = dst[e];
        int pos = atomicAdd(&g_cursor[d], 1);
        g_csr_src[pos] = src[e];
    }
}

// ---------------------------------------------------------------------------
// GEMM1: h1[N,128] = x[N,165] @ W1[165,128]  (fp32 SIMT, 128x128 tile, 8x8/thr,
//        LDS.128 fragment loads)
// ---------------------------------------------------------------------------
__global__ void gemm1_kernel(const float* __restrict__ X, const float* __restrict__ W) {
    __shared__ __align__(16) float As[8][132];   // [k][row], row stride 132 (528B, 16B mult)
    __shared__ __align__(16) float Bs[8][128];   // [k][col]
    const int row0 = blockIdx.x * 128;
    const int tid  = threadIdx.x;          // 0..255
    const int tr   = tid >> 4;             // 0..15
    const int tc   = tid & 15;             // 0..15

    float acc[8][8];
#pragma unroll
    for (int i = 0; i < 8; i++)
#pragma unroll
        for (int j = 0; j < 8; j++) acc[i][j] = 0.f;

    for (int k0 = 0; k0 < IN_DIM; k0 += 8) {
#pragma unroll
        for (int t = 0; t < 4; t++) {
            int i = tid + t * 256;
            int r = i >> 3, c = i & 7;
            int gr = row0 + r, gc = k0 + c;
            As[c][r] = (gr < N_NODES && gc < IN_DIM) ? X[(size_t)gr * IN_DIM + gc] : 0.f;
        }
#pragma unroll
        for (int t = 0; t < 4; t++) {
            int i = tid + t * 256;
            int r = i >> 7, c = i & 127;
            int gk = k0 + r;
            Bs[r][c] = (gk < IN_DIM) ? W[gk * HIDDEN + c] : 0.f;
        }
        __syncthreads();
#pragma unroll
        for (int k = 0; k < 8; k++) {
            float4 a0 = *(const float4*)&As[k][tr * 8];
            float4 a1 = *(const float4*)&As[k][tr * 8 + 4];
            float4 b0 = *(const float4*)&Bs[k][tc * 8];
            float4 b1 = *(const float4*)&Bs[k][tc * 8 + 4];
            float a[8] = {a0.x, a0.y, a0.z, a0.w, a1.x, a1.y, a1.z, a1.w};
            float b[8] = {b0.x, b0.y, b0.z, b0.w, b1.x, b1.y, b1.z, b1.w};
#pragma unroll
            for (int i = 0; i < 8; i++)
#pragma unroll
                for (int j = 0; j < 8; j++) acc[i][j] = fmaf(a[i], b[j], acc[i][j]);
        }
        __syncthreads();
    }

#pragma unroll
    for (int i = 0; i < 8; i++) {
        int gr = row0 + tr * 8 + i;
        if (gr < N_NODES) {
            float* o = g_h1 + (size_t)gr * HIDDEN + tc * 8;
            *(float4*)(o)     = make_float4(acc[i][0], acc[i][1], acc[i][2], acc[i][3]);
            *(float4*)(o + 4) = make_float4(acc[i][4], acc[i][5], acc[i][6], acc[i][7]);
        }
    }
}

// ---------------------------------------------------------------------------
// agg1 (CSR): one warp per node; lanes hold float4 accumulators over 128 feats.
// acc = sum_{s in row} dinv[s] * h1[s];  agg1[d] = dinv[d] * acc
// (self-loop is a regular CSR entry: dinv[d]*dinv[d]*h1[d] falls out naturally)
// ---------------------------------------------------------------------------
__global__ void agg1_csr_kernel() {
    int warp = (blockIdx.x * blockDim.x + threadIdx.x) >> 5;
    int lane = threadIdx.x & 31;
    if (warp >= N_NODES) return;
    int node  = warp;
    int start = g_rowstart[node];
    int end   = g_rowstart[node + 1];

    float4 acc = make_float4(0.f, 0.f, 0.f, 0.f);

    for (int base = start; base < end; base += 32) {
        int idx = base + lane;
        int   s_l = 0;
        float d_l = 0.f;
        if (idx < end) {
            s_l = g_csr_src[idx];
            d_l = g_dinv[s_l];
        }
        int m = min(32, end - base);
        for (int j = 0; j < m; j++) {
            int   s = __shfl_sync(0xffffffffu, s_l, j);
            float w = __shfl_sync(0xffffffffu, d_l, j);
            float4 v = ((const float4*)(g_h1 + (size_t)s * HIDDEN))[lane];
            acc.x = fmaf(w, v.x, acc.x);
            acc.y = fmaf(w, v.y, acc.y);
            acc.z = fmaf(w, v.z, acc.z);
            acc.w = fmaf(w, v.w, acc.w);
        }
    }

    float dd = g_dinv[node];
    acc.x *= dd; acc.y *= dd; acc.z *= dd; acc.w *= dd;
    ((float4*)(g_agg1 + (size_t)node * HIDDEN))[lane] = acc;
}

// ---------------------------------------------------------------------------
// layer2: h2 = relu(agg1 + b1) @ W2   (one warp per node)
// ---------------------------------------------------------------------------
__global__ void layer2_kernel(const float* __restrict__ b1,
                              const float* __restrict__ W2) {
    int gtid = blockIdx.x * blockDim.x + threadIdx.x;
    if (gtid >= N_NODES * 32) return;
    int node = gtid >> 5, lane = gtid & 31;
    float4 h  = ((const float4*)(g_agg1 + (size_t)node * HIDDEN))[lane];
    float4 bb = ((const float4*)b1)[lane];
    h.x = fmaxf(h.x + bb.x, 0.f);
    h.y = fmaxf(h.y + bb.y, 0.f);
    h.z = fmaxf(h.z + bb.z, 0.f);
    h.w = fmaxf(h.w + bb.w, 0.f);
    // W2 row-major [128][2]; lane's features 4lane..4lane+3 => 8 floats
    const float4* wv = (const float4*)W2;
    float4 wa = wv[2 * lane], wb = wv[2 * lane + 1];
    float o0 = h.x * wa.x + h.y * wa.z + h.z * wb.x + h.w * wb.z;
    float o1 = h.x * wa.y + h.y * wa.w + h.z * wb.y + h.w * wb.w;
#pragma unroll
    for (int off = 16; off; off >>= 1) {
        o0 += __shfl_xor_sync(0xffffffffu, o0, off);
        o1 += __shfl_xor_sync(0xffffffffu, o1, off);
    }
    if (lane == 0) {
        g_h2[2 * node]     = o0;
        g_h2[2 * node + 1] = o1;
    }
}

// ---------------------------------------------------------------------------
// agg2 (CSR): one warp per node on 2-dim features; lanes parallel over edges.
// out[d] = dinv[d] * sum_{s in row} dinv[s]*h2[s] + b2
// ---------------------------------------------------------------------------
__global__ void agg2_csr_kernel(const float* __restrict__ b2,
                                float* __restrict__ out) {
    int warp = (blockIdx.x * blockDim.x + threadIdx.x) >> 5;
    int lane = threadIdx.x & 31;
    if (warp >= N_NODES) return;
    int node  = warp;
    int start = g_rowstart[node];
    int end   = g_rowstart[node + 1];

    float a0 = 0.f, a1 = 0.f;
    for (int idx = start + lane; idx < end; idx += 32) {
        int s    = g_csr_src[idx];
        float w  = g_dinv[s];
        float2 h = *(const float2*)(g_h2 + 2 * (size_t)s);
        a0 = fmaf(w, h.x, a0);
        a1 = fmaf(w, h.y, a1);
    }
#pragma unroll
    for (int off = 16; off; off >>= 1) {
        a0 += __shfl_xor_sync(0xffffffffu, a0, off);
        a1 += __shfl_xor_sync(0xffffffffu, a1, off);
    }
    if (lane == 0) {
        float dd = g_dinv[node];
        out[2 * node]     = fmaf(dd, a0, b2[0]);
        out[2 * node + 1] = fmaf(dd, a1, b2[1]);
    }
}

// ---------------------------------------------------------------------------
extern "C" void kernel_launch(void* const* d_in, const int* in_sizes, int n_in,
                              void* d_out, int out_size) {
    const float* x  = (const float*)d_in[0];
    const int*   ei = (const int*)d_in[1];
    const float* W1 = (const float*)d_in[2];
    const float* b1 = (const float*)d_in[3];
    const float* W2 = (const float*)d_in[4];
    const float* b2 = (const float*)d_in[5];
    float*       out = (float*)d_out;

    const int* src = ei;
    const int* dst = ei + N_EDGES;

    // CSR build (counting sort by dst, self-loops included)
    init_cnt_kernel<<<(N_NODES + 255) / 256, 256>>>();
    hist_kernel<<<(N_EDGES + 255) / 256, 256>>>(dst);
    dinv_kernel<<<(N_NODES + 255) / 256, 256>>>();
    scan1_kernel<<<NB_SCAN, SCAN_BLOCK>>>();
    scan2_kernel<<<1, SCAN_BLOCK>>>();
    scan3_kernel<<<(N_NODES + 1 + 255) / 256, 256>>>();
    fill_self_kernel<<<(N_NODES + 255) / 256, 256>>>();
    fill_edges_kernel<<<(N_EDGES + 255) / 256, 256>>>(src, dst);

    // layer 1
    gemm1_kernel<<<(N_NODES + 127) / 128, 256>>>(x, W1);
    agg1_csr_kernel<<<(N_NODES * 32 + 255) / 256, 256>>>();

    // layer 2
    layer2_kernel<<<(N_NODES * 32 + 255) / 256, 256>>>(b1, W2);
    agg2_csr_kernel<<<(N_NODES * 32 + 255) / 256, 256>>>(b2, out);
}

// round 4
// speedup vs baseline: 1.7841x; 1.4853x over previous
#include <cuda_runtime.h>
#include <mma.h>
#include <cstdint>

using namespace nvcuda;

#define N_NODES 100000
#define N_EDGES 1600000
#define IN_DIM  165
#define HIDDEN  128
#define OUT_DIM 2

#define SCAN_BLOCK 512
#define NB_SCAN ((N_NODES + SCAN_BLOCK - 1) / SCAN_BLOCK)   // 196

// ---------------------------------------------------------------------------
// Static scratch  (g_h1 padded: wmma stores full 16x16 tiles past row 100000)
// ---------------------------------------------------------------------------
__device__ float g_h1[(size_t)(N_NODES + 128) * HIDDEN];
__device__ float g_h2[(size_t)N_NODES * OUT_DIM];
__device__ float g_dinv[N_NODES];
__device__ int   g_cnt[N_NODES];
__device__ int   g_rowstart[N_NODES + 1];
__device__ int   g_cursor[N_NODES];
__device__ int   g_bsum[NB_SCAN];
__device__ int   g_bsum_ex[NB_SCAN];
__device__ int   g_csr_src[N_EDGES + N_NODES];

__device__ __forceinline__ float to_tf32(float x) {
    float y;
    asm("cvt.rna.tf32.f32 %0, %1;" : "=f"(y) : "f"(x));
    return y;
}

// ---------------------------------------------------------------------------
// degree / CSR build (counting sort by dst; self-loop is a regular entry)
// ---------------------------------------------------------------------------
__global__ void init_cnt_kernel() {
    int i = blockIdx.x * blockDim.x + threadIdx.x;
    if (i < N_NODES) g_cnt[i] = 1;
}

__global__ void hist_kernel(const int* __restrict__ dst) {
    int e = blockIdx.x * blockDim.x + threadIdx.x;
    if (e < N_EDGES) atomicAdd(&g_cnt[dst[e]], 1);
}

__global__ void dinv_kernel() {
    int i = blockIdx.x * blockDim.x + threadIdx.x;
    if (i < N_NODES) g_dinv[i] = rsqrtf((float)g_cnt[i]);
}

__global__ void scan1_kernel() {
    __shared__ int s0[SCAN_BLOCK], s1[SCAN_BLOCK];
    int t = threadIdx.x;
    int i = blockIdx.x * SCAN_BLOCK + t;
    int v = (i < N_NODES) ? g_cnt[i] : 0;
    int* a = s0; int* b = s1;
    a[t] = v;
    __syncthreads();
#pragma unroll
    for (int off = 1; off < SCAN_BLOCK; off <<= 1) {
        b[t] = (t >= off) ? a[t] + a[t - off] : a[t];
        __syncthreads();
        int* tmp = a; a = b; b = tmp;
    }
    if (i < N_NODES) g_rowstart[i] = a[t] - v;
    if (t == SCAN_BLOCK - 1) g_bsum[blockIdx.x] = a[t];
}

__global__ void scan2_kernel() {
    __shared__ int s0[SCAN_BLOCK], s1[SCAN_BLOCK];
    int t = threadIdx.x;
    int v = (t < NB_SCAN) ? g_bsum[t] : 0;
    int* a = s0; int* b = s1;
    a[t] = v;
    __syncthreads();
#pragma unroll
    for (int off = 1; off < SCAN_BLOCK; off <<= 1) {
        b[t] = (t >= off) ? a[t] + a[t - off] : a[t];
        __syncthreads();
        int* tmp = a; a = b; b = tmp;
    }
    if (t < NB_SCAN) g_bsum_ex[t] = a[t] - v;
}

__global__ void scan3_kernel() {
    int i = blockIdx.x * blockDim.x + threadIdx.x;
    if (i < N_NODES) {
        int r = g_rowstart[i] + g_bsum_ex[i / SCAN_BLOCK];
        g_rowstart[i] = r;
        g_cursor[i]   = r;
    } else if (i == N_NODES) {
        g_rowstart[N_NODES] = N_EDGES + N_NODES;
    }
}

__global__ void fill_self_kernel() {
    int i = blockIdx.x * blockDim.x + threadIdx.x;
    if (i < N_NODES) {
        int pos = atomicAdd(&g_cursor[i], 1);
        g_csr_src[pos] = i;
    }
}

__global__ void fill_edges_kernel(const int* __restrict__ src,
                                  const int* __restrict__ dst) {
    int e = blockIdx.x * blockDim.x + threadIdx.x;
    if (e < N_EDGES) {
        int d   = dst[e];
        int pos = atomicAdd(&g_cursor[d], 1);
        g_csr_src[pos] = src[e];
    }
}

// ---------------------------------------------------------------------------
// GEMM1 (tf32 wmma): h1[N,128] = x[N,165] @ W1[165,128]
// block tile 128x128, 8 warps (4M x 2N), warp tile 32x64, k-step 8
// ---------------------------------------------------------------------------
__global__ void gemm1_tf32_kernel(const float* __restrict__ X,
                                  const float* __restrict__ W) {
    __shared__ __align__(16) float As[128][8];    // [m][k]
    __shared__ __align__(16) float Bs[8][132];    // [k][n], padded
    const int tid    = threadIdx.x;              // 0..255
    const int wid    = tid >> 5;
    const int warp_m = wid & 3;                  // 0..3 -> 32 rows each
    const int warp_n = wid >> 2;                 // 0..1 -> 64 cols each
    const int row0   = blockIdx.x * 128;

    wmma::fragment<wmma::accumulator, 16, 16, 8, float> acc[2][4];
#pragma unroll
    for (int i = 0; i < 2; i++)
#pragma unroll
        for (int j = 0; j < 4; j++) wmma::fill_fragment(acc[i][j], 0.f);

    for (int k0 = 0; k0 < 168; k0 += 8) {
        // A tile: 128x8
#pragma unroll
        for (int t = 0; t < 4; t++) {
            int idx = tid + t * 256;
            int r = idx >> 3, c = idx & 7;
            int gr = row0 + r, gc = k0 + c;
            float v = (gr < N_NODES && gc < IN_DIM) ? X[(size_t)gr * IN_DIM + gc] : 0.f;
            As[r][c] = to_tf32(v);
        }
        // B tile: 8x128
#pragma unroll
        for (int t = 0; t < 4; t++) {
            int idx = tid + t * 256;
            int r = idx >> 7, c = idx & 127;
            int gk = k0 + r;
            float v = (gk < IN_DIM) ? W[gk * HIDDEN + c] : 0.f;
            Bs[r][c] = to_tf32(v);
        }
        __syncthreads();

        wmma::fragment<wmma::matrix_a, 16, 16, 8, wmma::precision::tf32, wmma::row_major> af[2];
        wmma::fragment<wmma::matrix_b, 16, 16, 8, wmma::precision::tf32, wmma::row_major> bf[4];
#pragma unroll
        for (int i = 0; i < 2; i++)
            wmma::load_matrix_sync(af[i], &As[warp_m * 32 + i * 16][0], 8);
#pragma unroll
        for (int j = 0; j < 4; j++)
            wmma::load_matrix_sync(bf[j], &Bs[0][warp_n * 64 + j * 16], 132);
#pragma unroll
        for (int i = 0; i < 2; i++)
#pragma unroll
            for (int j = 0; j < 4; j++)
                wmma::mma_sync(acc[i][j], af[i], bf[j], acc[i][j]);
        __syncthreads();
    }

#pragma unroll
    for (int i = 0; i < 2; i++) {
        int r = row0 + warp_m * 32 + i * 16;
#pragma unroll
        for (int j = 0; j < 4; j++) {
            int c = warp_n * 64 + j * 16;
            wmma::store_matrix_sync(&g_h1[(size_t)r * HIDDEN + c], acc[i][j],
                                    HIDDEN, wmma::mem_row_major);
        }
    }
}

// ---------------------------------------------------------------------------
// agg1 + layer2 fused (CSR): one warp per node.
// acc = dinv[d] * sum_{s in row} dinv[s]*h1[s]; then relu(acc+b1) @ W2 -> h2[d]
// ---------------------------------------------------------------------------
__global__ void agg1_fused_kernel(const float* __restrict__ b1,
                                  const float* __restrict__ W2) {
    int warp = (blockIdx.x * blockDim.x + threadIdx.x) >> 5;
    int lane = threadIdx.x & 31;
    if (warp >= N_NODES) return;
    int node  = warp;
    int start = g_rowstart[node];
    int end   = g_rowstart[node + 1];

    float4 acc = make_float4(0.f, 0.f, 0.f, 0.f);

    for (int base = start; base < end; base += 32) {
        int idx = base + lane;
        int   s_l = 0;
        float d_l = 0.f;
        if (idx < end) {
            s_l = g_csr_src[idx];
            d_l = g_dinv[s_l];
        }
        int m = min(32, end - base);
        int j = 0;
        for (; j + 4 <= m; j += 4) {
            int   s0 = __shfl_sync(0xffffffffu, s_l, j);
            int   s1 = __shfl_sync(0xffffffffu, s_l, j + 1);
            int   s2 = __shfl_sync(0xffffffffu, s_l, j + 2);
            int   s3 = __shfl_sync(0xffffffffu, s_l, j + 3);
            float w0 = __shfl_sync(0xffffffffu, d_l, j);
            float w1 = __shfl_sync(0xffffffffu, d_l, j + 1);
            float w2 = __shfl_sync(0xffffffffu, d_l, j + 2);
            float w3 = __shfl_sync(0xffffffffu, d_l, j + 3);
            float4 v0 = ((const float4*)(g_h1 + (size_t)s0 * HIDDEN))[lane];
            float4 v1 = ((const float4*)(g_h1 + (size_t)s1 * HIDDEN))[lane];
            float4 v2 = ((const float4*)(g_h1 + (size_t)s2 * HIDDEN))[lane];
            float4 v3 = ((const float4*)(g_h1 + (size_t)s3 * HIDDEN))[lane];
            acc.x = fmaf(w0, v0.x, acc.x); acc.y = fmaf(w0, v0.y, acc.y);
            acc.z = fmaf(w0, v0.z, acc.z); acc.w = fmaf(w0, v0.w, acc.w);
            acc.x = fmaf(w1, v1.x, acc.x); acc.y = fmaf(w1, v1.y, acc.y);
            acc.z = fmaf(w1, v1.z, acc.z); acc.w = fmaf(w1, v1.w, acc.w);
            acc.x = fmaf(w2, v2.x, acc.x); acc.y = fmaf(w2, v2.y, acc.y);
            acc.z = fmaf(w2, v2.z, acc.z); acc.w = fmaf(w2, v2.w, acc.w);
            acc.x = fmaf(w3, v3.x, acc.x); acc.y = fmaf(w3, v3.y, acc.y);
            acc.z = fmaf(w3, v3.z, acc.z); acc.w = fmaf(w3, v3.w, acc.w);
        }
        for (; j < m; j++) {
            int   s = __shfl_sync(0xffffffffu, s_l, j);
            float w = __shfl_sync(0xffffffffu, d_l, j);
            float4 v = ((const float4*)(g_h1 + (size_t)s * HIDDEN))[lane];
            acc.x = fmaf(w, v.x, acc.x); acc.y = fmaf(w, v.y, acc.y);
            acc.z = fmaf(w, v.z, acc.z); acc.w = fmaf(w, v.w, acc.w);
        }
    }

    // epilogue: * dinv[d], + b1, relu, @ W2 (lane owns feats 4*lane..4*lane+3)
    float dd = g_dinv[node];
    float4 bb = ((const float4*)b1)[lane];
    float h0 = fmaxf(fmaf(dd, acc.x, bb.x), 0.f);
    float h1v = fmaxf(fmaf(dd, acc.y, bb.y), 0.f);
    float h2v = fmaxf(fmaf(dd, acc.z, bb.z), 0.f);
    float h3 = fmaxf(fmaf(dd, acc.w, bb.w), 0.f);
    const float4* wv = (const float4*)W2;   // [128][2] row-major
    float4 wa = wv[2 * lane], wb = wv[2 * lane + 1];
    float o0 = h0 * wa.x + h1v * wa.z + h2v * wb.x + h3 * wb.z;
    float o1 = h0 * wa.y + h1v * wa.w + h2v * wb.y + h3 * wb.w;
#pragma unroll
    for (int off = 16; off; off >>= 1) {
        o0 += __shfl_xor_sync(0xffffffffu, o0, off);
        o1 += __shfl_xor_sync(0xffffffffu, o1, off);
    }
    if (lane == 0) {
        g_h2[2 * node]     = o0;
        g_h2[2 * node + 1] = o1;
    }
}

// ---------------------------------------------------------------------------
// agg2 (CSR): one warp per node, 2-dim features, lanes parallel over edges
// ---------------------------------------------------------------------------
__global__ void agg2_csr_kernel(const float* __restrict__ b2,
                                float* __restrict__ out) {
    int warp = (blockIdx.x * blockDim.x + threadIdx.x) >> 5;
    int lane = threadIdx.x & 31;
    if (warp >= N_NODES) return;
    int node  = warp;
    int start = g_rowstart[node];
    int end   = g_rowstart[node + 1];

    float a0 = 0.f, a1 = 0.f;
    for (int idx = start + lane; idx < end; idx += 32) {
        int s    = g_csr_src[idx];
        float w  = g_dinv[s];
        float2 h = *(const float2*)(g_h2 + 2 * (size_t)s);
        a0 = fmaf(w, h.x, a0);
        a1 = fmaf(w, h.y, a1);
    }
#pragma unroll
    for (int off = 16; off; off >>= 1) {
        a0 += __shfl_xor_sync(0xffffffffu, a0, off);
        a1 += __shfl_xor_sync(0xffffffffu, a1, off);
    }
    if (lane == 0) {
        float dd = g_dinv[node];
        out[2 * node]     = fmaf(dd, a0, b2[0]);
        out[2 * node + 1] = fmaf(dd, a1, b2[1]);
    }
}

// ---------------------------------------------------------------------------
extern "C" void kernel_launch(void* const* d_in, const int* in_sizes, int n_in,
                              void* d_out, int out_size) {
    const float* x  = (const float*)d_in[0];
    const int*   ei = (const int*)d_in[1];
    const float* W1 = (const float*)d_in[2];
    const float* b1 = (const float*)d_in[3];
    const float* W2 = (const float*)d_in[4];
    const float* b2 = (const float*)d_in[5];
    float*       out = (float*)d_out;

    const int* src = ei;
    const int* dst = ei + N_EDGES;

    // CSR build
    init_cnt_kernel<<<(N_NODES + 255) / 256, 256>>>();
    hist_kernel<<<(N_EDGES + 255) / 256, 256>>>(dst);
    dinv_kernel<<<(N_NODES + 255) / 256, 256>>>();
    scan1_kernel<<<NB_SCAN, SCAN_BLOCK>>>();
    scan2_kernel<<<1, SCAN_BLOCK>>>();
    scan3_kernel<<<(N_NODES + 1 + 255) / 256, 256>>>();
    fill_self_kernel<<<(N_NODES + 255) / 256, 256>>>();
    fill_edges_kernel<<<(N_EDGES + 255) / 256, 256>>>(src, dst);

    // layer 1 (GEMM overlaps CSR build on the same stream order; independent until agg1)
    gemm1_tf32_kernel<<<(N_NODES + 127) / 128, 256>>>(x, W1);

    // layer 1 aggregate + layer 2 transform (fused)
    agg1_fused_kernel<<<(N_NODES * 32 + 255) / 256, 256>>>(b1, W2);

    // layer 2 aggregate
    agg2_csr_kernel<<<(N_NODES * 32 + 255) / 256, 256>>>(b2, out);
}

// round 6
// speedup vs baseline: 2.0585x; 1.1538x over previous
#include <cuda_runtime.h>
#include <cuda_fp16.h>
#include <mma.h>
#include <cstdint>

using namespace nvcuda;

#define N_NODES 100000
#define N_EDGES 1600000
#define IN_DIM  165
#define HIDDEN  128
#define OUT_DIM 2

#define SCAN_BLOCK 512
#define NB_SCAN ((N_NODES + SCAN_BLOCK - 1) / SCAN_BLOCK)   // 196

// ---------------------------------------------------------------------------
// Static scratch
// ---------------------------------------------------------------------------
__device__ __align__(16) __half g_h1h[(size_t)N_NODES * HIDDEN];  // dinv-scaled fp16 h1
__device__ float g_h2s[(size_t)N_NODES * OUT_DIM];                // dinv-scaled h2
__device__ float g_dinv[N_NODES];
__device__ int   g_cnt[N_NODES];                                  // in-edge count (excl self)
__device__ int   g_rowstart[N_NODES + 1];
__device__ int   g_cursor[N_NODES];
__device__ int   g_bsum[NB_SCAN];
__device__ int   g_bsum_ex[NB_SCAN];
__device__ int   g_csr_src[N_EDGES];

__device__ __forceinline__ float to_tf32(float x) {
    float y;
    asm("cvt.rna.tf32.f32 %0, %1;" : "=f"(y) : "f"(x));
    return y;
}

// ---------------------------------------------------------------------------
// degree / CSR build (counting sort by dst; self-loops handled in epilogues)
// ---------------------------------------------------------------------------
__global__ void zero_cnt_kernel() {
    int i = blockIdx.x * blockDim.x + threadIdx.x;
    if (i < N_NODES) g_cnt[i] = 0;
}

__global__ void hist_kernel(const int* __restrict__ dst) {
    int e = blockIdx.x * blockDim.x + threadIdx.x;
    if (e < N_EDGES) atomicAdd(&g_cnt[dst[e]], 1);
}

__global__ void dinv_kernel() {
    int i = blockIdx.x * blockDim.x + threadIdx.x;
    if (i < N_NODES) g_dinv[i] = rsqrtf((float)(g_cnt[i] + 1));  // +1 = self-loop
}

__global__ void scan1_kernel() {
    __shared__ int s0[SCAN_BLOCK], s1[SCAN_BLOCK];
    int t = threadIdx.x;
    int i = blockIdx.x * SCAN_BLOCK + t;
    int v = (i < N_NODES) ? g_cnt[i] : 0;
    int* a = s0; int* b = s1;
    a[t] = v;
    __syncthreads();
#pragma unroll
    for (int off = 1; off < SCAN_BLOCK; off <<= 1) {
        b[t] = (t >= off) ? a[t] + a[t - off] : a[t];
        __syncthreads();
        int* tmp = a; a = b; b = tmp;
    }
    if (i < N_NODES) g_rowstart[i] = a[t] - v;
    if (t == SCAN_BLOCK - 1) g_bsum[blockIdx.x] = a[t];
}

__global__ void scan2_kernel() {
    __shared__ int s0[SCAN_BLOCK], s1[SCAN_BLOCK];
    int t = threadIdx.x;
    int v = (t < NB_SCAN) ? g_bsum[t] : 0;
    int* a = s0; int* b = s1;
    a[t] = v;
    __syncthreads();
#pragma unroll
    for (int off = 1; off < SCAN_BLOCK; off <<= 1) {
        b[t] = (t >= off) ? a[t] + a[t - off] : a[t];
        __syncthreads();
        int* tmp = a; a = b; b = tmp;
    }
    if (t < NB_SCAN) g_bsum_ex[t] = a[t] - v;
}

__global__ void scan3_kernel() {
    int i = blockIdx.x * blockDim.x + threadIdx.x;
    if (i < N_NODES) {
        int r = g_rowstart[i] + g_bsum_ex[i / SCAN_BLOCK];
        g_rowstart[i] = r;
        g_cursor[i]   = r;
    } else if (i == N_NODES) {
        g_rowstart[N_NODES] = N_EDGES;
    }
}

__global__ void fill_edges_kernel(const int* __restrict__ src,
                                  const int* __restrict__ dst) {
    int e = blockIdx.x * blockDim.x + threadIdx.x;
    if (e < N_EDGES) {
        int d   = dst[e];
        int pos = atomicAdd(&g_cursor[d], 1);
        g_csr_src[pos] = src[e];
    }
}

// ---------------------------------------------------------------------------
// GEMM1 (tf32 wmma): h1h[r,:] = dinv[r] * (x[r,:] @ W1)  stored fp16
// block tile 128x128, 8 warps (4M x 2N), warp tile 32x64, k-step 8
// ---------------------------------------------------------------------------
__global__ void gemm1_tf32_kernel(const float* __restrict__ X,
                                  const float* __restrict__ W) {
    __shared__ __align__(16) float As[128][8];
    __shared__ __align__(16) float Bs[8][132];
    __shared__ __align__(16) float stage[8][16][20];  // ldm=20: multiple of 4 (wmma req)
    const int tid    = threadIdx.x;
    const int wid    = tid >> 5;
    const int lane   = tid & 31;
    const int warp_m = wid & 3;
    const int warp_n = wid >> 2;
    const int row0   = blockIdx.x * 128;

    wmma::fragment<wmma::accumulator, 16, 16, 8, float> acc[2][4];
#pragma unroll
    for (int i = 0; i < 2; i++)
#pragma unroll
        for (int j = 0; j < 4; j++) wmma::fill_fragment(acc[i][j], 0.f);

    for (int k0 = 0; k0 < 168; k0 += 8) {
#pragma unroll
        for (int t = 0; t < 4; t++) {
            int idx = tid + t * 256;
            int r = idx >> 3, c = idx & 7;
            int gr = row0 + r, gc = k0 + c;
            float v = (gr < N_NODES && gc < IN_DIM) ? X[(size_t)gr * IN_DIM + gc] : 0.f;
            As[r][c] = to_tf32(v);
        }
#pragma unroll
        for (int t = 0; t < 4; t++) {
            int idx = tid + t * 256;
            int r = idx >> 7, c = idx & 127;
            int gk = k0 + r;
            float v = (gk < IN_DIM) ? W[gk * HIDDEN + c] : 0.f;
            Bs[r][c] = to_tf32(v);
        }
        __syncthreads();

        wmma::fragment<wmma::matrix_a, 16, 16, 8, wmma::precision::tf32, wmma::row_major> af[2];
        wmma::fragment<wmma::matrix_b, 16, 16, 8, wmma::precision::tf32, wmma::row_major> bf[4];
#pragma unroll
        for (int i = 0; i < 2; i++)
            wmma::load_matrix_sync(af[i], &As[warp_m * 32 + i * 16][0], 8);
#pragma unroll
        for (int j = 0; j < 4; j++)
            wmma::load_matrix_sync(bf[j], &Bs[0][warp_n * 64 + j * 16], 132);
#pragma unroll
        for (int i = 0; i < 2; i++)
#pragma unroll
            for (int j = 0; j < 4; j++)
                wmma::mma_sync(acc[i][j], af[i], bf[j], acc[i][j]);
        __syncthreads();
    }

    // epilogue: stage each 16x16 tile, scale by dinv[row], convert fp16, store
#pragma unroll
    for (int i = 0; i < 2; i++) {
#pragma unroll
        for (int j = 0; j < 4; j++) {
            wmma::store_matrix_sync(&stage[wid][0][0], acc[i][j], 20, wmma::mem_row_major);
            __syncwarp();
            int r = row0 + warp_m * 32 + i * 16 + (lane >> 1);
            int c = warp_n * 64 + j * 16 + (lane & 1) * 8;
            if (r < N_NODES) {
                float di = g_dinv[r];
                const float* sp = &stage[wid][lane >> 1][(lane & 1) * 8];
                __half2 p0 = __floats2half2_rn(sp[0] * di, sp[1] * di);
                __half2 p1 = __floats2half2_rn(sp[2] * di, sp[3] * di);
                __half2 p2 = __floats2half2_rn(sp[4] * di, sp[5] * di);
                __half2 p3 = __floats2half2_rn(sp[6] * di, sp[7] * di);
                uint4 pk;
                pk.x = *(const uint32_t*)&p0;
                pk.y = *(const uint32_t*)&p1;
                pk.z = *(const uint32_t*)&p2;
                pk.w = *(const uint32_t*)&p3;
                *(uint4*)&g_h1h[(size_t)r * HIDDEN + c] = pk;
            }
            __syncwarp();
        }
    }
}

// ---------------------------------------------------------------------------
// agg1 + layer2 fused (CSR): one warp per node, lane owns feats 4L..4L+3.
// acc = h1s[node] + sum_{s in row} h1s[s]  (h1s already dinv[s]-scaled)
// agg = dinv[node]*acc;  h = relu(agg+b1);  h2s[node] = dinv[node]*(h@W2)
// ---------------------------------------------------------------------------
__global__ void agg1_fused_kernel(const float* __restrict__ b1,
                                  const float* __restrict__ W2) {
    int warp = (blockIdx.x * blockDim.x + threadIdx.x) >> 5;
    int lane = threadIdx.x & 31;
    if (warp >= N_NODES) return;
    int node  = warp;
    int start = g_rowstart[node];
    int end   = g_rowstart[node + 1];

    float4 acc;
    {   // self-loop term
        uint2 v = ((const uint2*)(g_h1h + (size_t)node * HIDDEN))[lane];
        float2 f0 = __half22float2(*reinterpret_cast<__half2*>(&v.x));
        float2 f1 = __half22float2(*reinterpret_cast<__half2*>(&v.y));
        acc = make_float4(f0.x, f0.y, f1.x, f1.y);
    }

    for (int base = start; base < end; base += 32) {
        int idx = base + lane;
        int s_l = (idx < end) ? g_csr_src[idx] : 0;
        int m = min(32, end - base);
        int j = 0;
        for (; j + 4 <= m; j += 4) {
            int s0 = __shfl_sync(0xffffffffu, s_l, j);
            int s1 = __shfl_sync(0xffffffffu, s_l, j + 1);
            int s2 = __shfl_sync(0xffffffffu, s_l, j + 2);
            int s3 = __shfl_sync(0xffffffffu, s_l, j + 3);
            uint2 v0 = ((const uint2*)(g_h1h + (size_t)s0 * HIDDEN))[lane];
            uint2 v1 = ((const uint2*)(g_h1h + (size_t)s1 * HIDDEN))[lane];
            uint2 v2 = ((const uint2*)(g_h1h + (size_t)s2 * HIDDEN))[lane];
            uint2 v3 = ((const uint2*)(g_h1h + (size_t)s3 * HIDDEN))[lane];
            float2 a0 = __half22float2(*reinterpret_cast<__half2*>(&v0.x));
            float2 a1 = __half22float2(*reinterpret_cast<__half2*>(&v0.y));
            float2 b0 = __half22float2(*reinterpret_cast<__half2*>(&v1.x));
            float2 b1f = __half22float2(*reinterpret_cast<__half2*>(&v1.y));
            float2 c0 = __half22float2(*reinterpret_cast<__half2*>(&v2.x));
            float2 c1 = __half22float2(*reinterpret_cast<__half2*>(&v2.y));
            float2 d0 = __half22float2(*reinterpret_cast<__half2*>(&v3.x));
            float2 d1 = __half22float2(*reinterpret_cast<__half2*>(&v3.y));
            acc.x += a0.x + b0.x + c0.x + d0.x;
            acc.y += a0.y + b0.y + c0.y + d0.y;
            acc.z += a1.x + b1f.x + c1.x + d1.x;
            acc.w += a1.y + b1f.y + c1.y + d1.y;
        }
        for (; j < m; j++) {
            int s = __shfl_sync(0xffffffffu, s_l, j);
            uint2 v = ((const uint2*)(g_h1h + (size_t)s * HIDDEN))[lane];
            float2 f0 = __half22float2(*reinterpret_cast<__half2*>(&v.x));
            float2 f1 = __half22float2(*reinterpret_cast<__half2*>(&v.y));
            acc.x += f0.x; acc.y += f0.y; acc.z += f1.x; acc.w += f1.y;
        }
    }

    float dd = g_dinv[node];
    float4 bb = ((const float4*)b1)[lane];
    float h0 = fmaxf(fmaf(dd, acc.x, bb.x), 0.f);
    float h1v = fmaxf(fmaf(dd, acc.y, bb.y), 0.f);
    float h2v = fmaxf(fmaf(dd, acc.z, bb.z), 0.f);
    float h3 = fmaxf(fmaf(dd, acc.w, bb.w), 0.f);
    const float4* wv = (const float4*)W2;   // [128][2] row-major
    float4 wa = wv[2 * lane], wb = wv[2 * lane + 1];
    float o0 = h0 * wa.x + h1v * wa.z + h2v * wb.x + h3 * wb.z;
    float o1 = h0 * wa.y + h1v * wa.w + h2v * wb.y + h3 * wb.w;
#pragma unroll
    for (int off = 16; off; off >>= 1) {
        o0 += __shfl_xor_sync(0xffffffffu, o0, off);
        o1 += __shfl_xor_sync(0xffffffffu, o1, off);
    }
    if (lane == 0) {
        g_h2s[2 * node]     = dd * o0;   // pre-scaled for layer-2 aggregation
        g_h2s[2 * node + 1] = dd * o1;
    }
}

// ---------------------------------------------------------------------------
// agg2 (CSR): one warp per node; out[d] = dinv[d]*(h2s[d] + sum h2s[s]) + b2
// ---------------------------------------------------------------------------
__global__ void agg2_csr_kernel(const float* __restrict__ b2,
                                float* __restrict__ out) {
    int warp = (blockIdx.x * blockDim.x + threadIdx.x) >> 5;
    int lane = threadIdx.x & 31;
    if (warp >= N_NODES) return;
    int node  = warp;
    int start = g_rowstart[node];
    int end   = g_rowstart[node + 1];

    float a0 = 0.f, a1 = 0.f;
    for (int idx = start + lane; idx < end; idx += 32) {
        int s    = g_csr_src[idx];
        float2 h = *(const float2*)(g_h2s + 2 * (size_t)s);
        a0 += h.x;
        a1 += h.y;
    }
#pragma unroll
    for (int off = 16; off; off >>= 1) {
        a0 += __shfl_xor_sync(0xffffffffu, a0, off);
        a1 += __shfl_xor_sync(0xffffffffu, a1, off);
    }
    if (lane == 0) {
        float2 hs = *(const float2*)(g_h2s + 2 * (size_t)node);  // self-loop
        float dd  = g_dinv[node];
        out[2 * node]     = fmaf(dd, a0 + hs.x, b2[0]);
        out[2 * node + 1] = fmaf(dd, a1 + hs.y, b2[1]);
    }
}

// ---------------------------------------------------------------------------
extern "C" void kernel_launch(void* const* d_in, const int* in_sizes, int n_in,
                              void* d_out, int out_size) {
    const float* x  = (const float*)d_in[0];
    const int*   ei = (const int*)d_in[1];
    const float* W1 = (const float*)d_in[2];
    const float* b1 = (const float*)d_in[3];
    const float* W2 = (const float*)d_in[4];
    const float* b2 = (const float*)d_in[5];
    float*       out = (float*)d_out;

    const int* src = ei;
    const int* dst = ei + N_EDGES;

    // degree / dinv
    zero_cnt_kernel<<<(N_NODES + 255) / 256, 256>>>();
    hist_kernel<<<(N_EDGES + 255) / 256, 256>>>(dst);
    dinv_kernel<<<(N_NODES + 255) / 256, 256>>>();

    // GEMM (needs dinv for the scaled epilogue)
    gemm1_tf32_kernel<<<(N_NODES + 127) / 128, 256>>>(x, W1);

    // CSR build (excl self-loops)
    scan1_kernel<<<NB_SCAN, SCAN_BLOCK>>>();
    scan2_kernel<<<1, SCAN_BLOCK>>>();
    scan3_kernel<<<(N_NODES + 1 + 255) / 256, 256>>>();
    fill_edges_kernel<<<(N_EDGES + 255) / 256, 256>>>(src, dst);

    // fused aggregate + layer-2 transform
    agg1_fused_kernel<<<(N_NODES * 32 + 255) / 256, 256>>>(b1, W2);

    // layer-2 aggregate
    agg2_csr_kernel<<<(N_NODES * 32 + 255) / 256, 256>>>(b2, out);
}

// round 8
// speedup vs baseline: 2.2010x; 1.0692x over previous
#include <cuda_runtime.h>
#include <cuda_fp16.h>
#include <mma.h>
#include <cstdint>

using namespace nvcuda;

#define N_NODES 100000
#define N_EDGES 1600000
#define IN_DIM  165
#define HIDDEN  128
#define OUT_DIM 2

#define SCAN_BLOCK 512
#define NB_SCAN ((N_NODES + SCAN_BLOCK - 1) / SCAN_BLOCK)   // 196

// ---------------------------------------------------------------------------
// Static scratch
// ---------------------------------------------------------------------------
__device__ __align__(16) __half g_h1h[(size_t)N_NODES * HIDDEN];  // dinv-scaled fp16 h1
__device__ float g_h2s[(size_t)N_NODES * OUT_DIM];                // dinv-scaled h2
__device__ float g_dinv[N_NODES];
__device__ int   g_cnt[N_NODES];
__device__ int   g_rowstart[N_NODES + 1];
__device__ int   g_cursor[N_NODES];
__device__ int   g_bsum[NB_SCAN];
__device__ int   g_bsum_ex[NB_SCAN];
__device__ int   g_csr_src[N_EDGES];

// 4-byte cp.async (.ca): X rows are only 4B-aligned (165 floats/row)
__device__ __forceinline__ void cp_async4(void* smem_dst, const void* gmem_src,
                                          int src_bytes) {
    uint32_t s = (uint32_t)__cvta_generic_to_shared(smem_dst);
    asm volatile("cp.async.ca.shared.global [%0], [%1], 4, %2;"
                 :: "r"(s), "l"(gmem_src), "r"(src_bytes));
}

// 16-byte cp.async (.cg): W rows are 512B — always 16B-aligned
__device__ __forceinline__ void cp_async16(void* smem_dst, const void* gmem_src,
                                           int src_bytes) {
    uint32_t s = (uint32_t)__cvta_generic_to_shared(smem_dst);
    asm volatile("cp.async.cg.shared.global [%0], [%1], 16, %2;"
                 :: "r"(s), "l"(gmem_src), "r"(src_bytes));
}

// ---------------------------------------------------------------------------
// degree / CSR build (counting sort by dst; self-loops handled in epilogues)
// ---------------------------------------------------------------------------
__global__ void zero_cnt_kernel() {
    int i = blockIdx.x * blockDim.x + threadIdx.x;
    if (i < N_NODES) g_cnt[i] = 0;
}

__global__ void hist_kernel(const int* __restrict__ dst) {
    int e = blockIdx.x * blockDim.x + threadIdx.x;
    if (e < N_EDGES) atomicAdd(&g_cnt[dst[e]], 1);
}

__global__ void dinv_kernel() {
    int i = blockIdx.x * blockDim.x + threadIdx.x;
    if (i < N_NODES) g_dinv[i] = rsqrtf((float)(g_cnt[i] + 1));  // +1 = self-loop
}

__global__ void scan1_kernel() {
    __shared__ int s0[SCAN_BLOCK], s1[SCAN_BLOCK];
    int t = threadIdx.x;
    int i = blockIdx.x * SCAN_BLOCK + t;
    int v = (i < N_NODES) ? g_cnt[i] : 0;
    int* a = s0; int* b = s1;
    a[t] = v;
    __syncthreads();
#pragma unroll
    for (int off = 1; off < SCAN_BLOCK; off <<= 1) {
        b[t] = (t >= off) ? a[t] + a[t - off] : a[t];
        __syncthreads();
        int* tmp = a; a = b; b = tmp;
    }
    if (i < N_NODES) g_rowstart[i] = a[t] - v;
    if (t == SCAN_BLOCK - 1) g_bsum[blockIdx.x] = a[t];
}

__global__ void scan2_kernel() {
    __shared__ int s0[SCAN_BLOCK], s1[SCAN_BLOCK];
    int t = threadIdx.x;
    int v = (t < NB_SCAN) ? g_bsum[t] : 0;
    int* a = s0; int* b = s1;
    a[t] = v;
    __syncthreads();
#pragma unroll
    for (int off = 1; off < SCAN_BLOCK; off <<= 1) {
        b[t] = (t >= off) ? a[t] + a[t - off] : a[t];
        __syncthreads();
        int* tmp = a; a = b; b = tmp;
    }
    if (t < NB_SCAN) g_bsum_ex[t] = a[t] - v;
}

__global__ void scan3_kernel() {
    int i = blockIdx.x * blockDim.x + threadIdx.x;
    if (i < N_NODES) {
        int r = g_rowstart[i] + g_bsum_ex[i / SCAN_BLOCK];
        g_rowstart[i] = r;
        g_cursor[i]   = r;
    } else if (i == N_NODES) {
        g_rowstart[N_NODES] = N_EDGES;
    }
}

__global__ void fill_edges_kernel(const int* __restrict__ src,
                                  const int* __restrict__ dst) {
    int e = blockIdx.x * blockDim.x + threadIdx.x;
    if (e < N_EDGES) {
        int d   = dst[e];
        int pos = atomicAdd(&g_cursor[d], 1);
        g_csr_src[pos] = src[e];
    }
}

// ---------------------------------------------------------------------------
// GEMM1 (tf32 wmma, double-buffered cp.async): h1h[r,:] = dinv[r]*(x@W1) fp16
// block tile 128x128, 8 warps (4M x 2N), k-step 16, 11 iters
// ---------------------------------------------------------------------------
#define KSTEP 16
#define NITER 11   // ceil(165/16)

__global__ void gemm1_tf32_kernel(const float* __restrict__ X,
                                  const float* __restrict__ W) {
    __shared__ __align__(16) float As[2][128][20];   // ldm 20
    __shared__ __align__(16) float Bs[2][16][132];   // ldm 132
    __shared__ __align__(16) float stage[8][16][20];
    const int tid    = threadIdx.x;
    const int wid    = tid >> 5;
    const int lane   = tid & 31;
    const int warp_m = wid & 3;
    const int warp_n = wid >> 2;
    const int row0   = blockIdx.x * 128;

    // A: 128x16 via 4B copies (2048 over 256 thr); B: 16x128 via 16B copies
    auto load_tiles = [&](int buf, int k0) {
#pragma unroll
        for (int t = 0; t < 8; t++) {
            int idx = tid + t * 256;
            int r = idx >> 4, c = idx & 15;
            int gr = row0 + r, gc = k0 + c;
            int nb = (gr < N_NODES && gc < IN_DIM) ? 4 : 0;
            cp_async4(&As[buf][r][c], X + (size_t)gr * IN_DIM + gc, nb);
        }
#pragma unroll
        for (int t = 0; t < 2; t++) {
            int idx = tid + t * 256;
            int r = idx >> 5, ch = idx & 31;
            int gk = k0 + r;
            int nb = (gk < IN_DIM) ? 16 : 0;
            cp_async16(&Bs[buf][r][ch * 4], W + (size_t)gk * HIDDEN + ch * 4, nb);
        }
    };

    wmma::fragment<wmma::accumulator, 16, 16, 8, float> acc[2][4];
#pragma unroll
    for (int i = 0; i < 2; i++)
#pragma unroll
        for (int j = 0; j < 4; j++) wmma::fill_fragment(acc[i][j], 0.f);

    load_tiles(0, 0);
    asm volatile("cp.async.commit_group;");

    for (int it = 0; it < NITER; it++) {
        if (it + 1 < NITER) {
            load_tiles((it + 1) & 1, (it + 1) * KSTEP);
            asm volatile("cp.async.commit_group;");
            asm volatile("cp.async.wait_group 1;");
        } else {
            asm volatile("cp.async.wait_group 0;");
        }
        __syncthreads();

        int buf = it & 1;
        wmma::fragment<wmma::matrix_a, 16, 16, 8, wmma::precision::tf32, wmma::row_major> af[2];
        wmma::fragment<wmma::matrix_b, 16, 16, 8, wmma::precision::tf32, wmma::row_major> bf[4];
#pragma unroll
        for (int kk = 0; kk < KSTEP; kk += 8) {
#pragma unroll
            for (int i = 0; i < 2; i++)
                wmma::load_matrix_sync(af[i], &As[buf][warp_m * 32 + i * 16][kk], 20);
#pragma unroll
            for (int j = 0; j < 4; j++)
                wmma::load_matrix_sync(bf[j], &Bs[buf][kk][warp_n * 64 + j * 16], 132);
#pragma unroll
            for (int i = 0; i < 2; i++)
#pragma unroll
                for (int j = 0; j < 4; j++)
                    wmma::mma_sync(acc[i][j], af[i], bf[j], acc[i][j]);
        }
        __syncthreads();
    }

    // epilogue: stage each 16x16 tile, scale by dinv[row], convert fp16, store
#pragma unroll
    for (int i = 0; i < 2; i++) {
#pragma unroll
        for (int j = 0; j < 4; j++) {
            wmma::store_matrix_sync(&stage[wid][0][0], acc[i][j], 20, wmma::mem_row_major);
            __syncwarp();
            int r = row0 + warp_m * 32 + i * 16 + (lane >> 1);
            int c = warp_n * 64 + j * 16 + (lane & 1) * 8;
            if (r < N_NODES) {
                float di = g_dinv[r];
                const float* sp = &stage[wid][lane >> 1][(lane & 1) * 8];
                __half2 p0 = __floats2half2_rn(sp[0] * di, sp[1] * di);
                __half2 p1 = __floats2half2_rn(sp[2] * di, sp[3] * di);
                __half2 p2 = __floats2half2_rn(sp[4] * di, sp[5] * di);
                __half2 p3 = __floats2half2_rn(sp[6] * di, sp[7] * di);
                uint4 pk;
                pk.x = *(const uint32_t*)&p0;
                pk.y = *(const uint32_t*)&p1;
                pk.z = *(const uint32_t*)&p2;
                pk.w = *(const uint32_t*)&p3;
                *(uint4*)&g_h1h[(size_t)r * HIDDEN + c] = pk;
            }
            __syncwarp();
        }
    }
}

// ---------------------------------------------------------------------------
// agg1 + layer2 fused (CSR): one warp per node, lane owns feats 4L..4L+3.
// ---------------------------------------------------------------------------
__global__ void agg1_fused_kernel(const float* __restrict__ b1,
                                  const float* __restrict__ W2) {
    int warp = (blockIdx.x * blockDim.x + threadIdx.x) >> 5;
    int lane = threadIdx.x & 31;
    if (warp >= N_NODES) return;
    int node  = warp;
    int start = g_rowstart[node];
    int end   = g_rowstart[node + 1];

    float4 acc;
    {   // self-loop term
        uint2 v = ((const uint2*)(g_h1h + (size_t)node * HIDDEN))[lane];
        float2 f0 = __half22float2(*reinterpret_cast<__half2*>(&v.x));
        float2 f1 = __half22float2(*reinterpret_cast<__half2*>(&v.y));
        acc = make_float4(f0.x, f0.y, f1.x, f1.y);
    }

    for (int base = start; base < end; base += 32) {
        int idx = base + lane;
        int s_l = (idx < end) ? g_csr_src[idx] : 0;
        int m = min(32, end - base);
        int j = 0;
        for (; j + 8 <= m; j += 8) {
            uint2 v[8];
#pragma unroll
            for (int u = 0; u < 8; u++) {
                int s = __shfl_sync(0xffffffffu, s_l, j + u);
                v[u] = ((const uint2*)(g_h1h + (size_t)s * HIDDEN))[lane];
            }
#pragma unroll
            for (int u = 0; u < 8; u++) {
                float2 f0 = __half22float2(*reinterpret_cast<__half2*>(&v[u].x));
                float2 f1 = __half22float2(*reinterpret_cast<__half2*>(&v[u].y));
                acc.x += f0.x; acc.y += f0.y; acc.z += f1.x; acc.w += f1.y;
            }
        }
        for (; j + 4 <= m; j += 4) {
            uint2 v[4];
#pragma unroll
            for (int u = 0; u < 4; u++) {
                int s = __shfl_sync(0xffffffffu, s_l, j + u);
                v[u] = ((const uint2*)(g_h1h + (size_t)s * HIDDEN))[lane];
            }
#pragma unroll
            for (int u = 0; u < 4; u++) {
                float2 f0 = __half22float2(*reinterpret_cast<__half2*>(&v[u].x));
                float2 f1 = __half22float2(*reinterpret_cast<__half2*>(&v[u].y));
                acc.x += f0.x; acc.y += f0.y; acc.z += f1.x; acc.w += f1.y;
            }
        }
        for (; j < m; j++) {
            int s = __shfl_sync(0xffffffffu, s_l, j);
            uint2 v = ((const uint2*)(g_h1h + (size_t)s * HIDDEN))[lane];
            float2 f0 = __half22float2(*reinterpret_cast<__half2*>(&v.x));
            float2 f1 = __half22float2(*reinterpret_cast<__half2*>(&v.y));
            acc.x += f0.x; acc.y += f0.y; acc.z += f1.x; acc.w += f1.y;
        }
    }

    float dd = g_dinv[node];
    float4 bb = ((const float4*)b1)[lane];
    float h0 = fmaxf(fmaf(dd, acc.x, bb.x), 0.f);
    float h1v = fmaxf(fmaf(dd, acc.y, bb.y), 0.f);
    float h2v = fmaxf(fmaf(dd, acc.z, bb.z), 0.f);
    float h3 = fmaxf(fmaf(dd, acc.w, bb.w), 0.f);
    const float4* wv = (const float4*)W2;   // [128][2] row-major
    float4 wa = wv[2 * lane], wb = wv[2 * lane + 1];
    float o0 = h0 * wa.x + h1v * wa.z + h2v * wb.x + h3 * wb.z;
    float o1 = h0 * wa.y + h1v * wa.w + h2v * wb.y + h3 * wb.w;
#pragma unroll
    for (int off = 16; off; off >>= 1) {
        o0 += __shfl_xor_sync(0xffffffffu, o0, off);
        o1 += __shfl_xor_sync(0xffffffffu, o1, off);
    }
    if (lane == 0) {
        g_h2s[2 * node]     = dd * o0;   // pre-scaled for layer-2 aggregation
        g_h2s[2 * node + 1] = dd * o1;
    }
}

// ---------------------------------------------------------------------------
// agg2 (CSR): one warp per node; out[d] = dinv[d]*(h2s[d] + sum h2s[s]) + b2
// ---------------------------------------------------------------------------
__global__ void agg2_csr_kernel(const float* __restrict__ b2,
                                float* __restrict__ out) {
    int warp = (blockIdx.x * blockDim.x + threadIdx.x) >> 5;
    int lane = threadIdx.x & 31;
    if (warp >= N_NODES) return;
    int node  = warp;
    int start = g_rowstart[node];
    int end   = g_rowstart[node + 1];

    float a0 = 0.f, a1 = 0.f;
    for (int idx = start + lane; idx < end; idx += 32) {
        int s    = g_csr_src[idx];
        float2 h = *(const float2*)(g_h2s + 2 * (size_t)s);
        a0 += h.x;
        a1 += h.y;
    }
#pragma unroll
    for (int off = 16; off; off >>= 1) {
        a0 += __shfl_xor_sync(0xffffffffu, a0, off);
        a1 += __shfl_xor_sync(0xffffffffu, a1, off);
    }
    if (lane == 0) {
        float2 hs = *(const float2*)(g_h2s + 2 * (size_t)node);  // self-loop
        float dd  = g_dinv[node];
        out[2 * node]     = fmaf(dd, a0 + hs.x, b2[0]);
        out[2 * node + 1] = fmaf(dd, a1 + hs.y, b2[1]);
    }
}

// ---------------------------------------------------------------------------
extern "C" void kernel_launch(void* const* d_in, const int* in_sizes, int n_in,
                              void* d_out, int out_size) {
    const float* x  = (const float*)d_in[0];
    const int*   ei = (const int*)d_in[1];
    const float* W1 = (const float*)d_in[2];
    const float* b1 = (const float*)d_in[3];
    const float* W2 = (const float*)d_in[4];
    const float* b2 = (const float*)d_in[5];
    float*       out = (float*)d_out;

    const int* src = ei;
    const int* dst = ei + N_EDGES;

    // degree / dinv
    zero_cnt_kernel<<<(N_NODES + 255) / 256, 256>>>();
    hist_kernel<<<(N_EDGES + 255) / 256, 256>>>(dst);
    dinv_kernel<<<(N_NODES + 255) / 256, 256>>>();

    // GEMM (needs dinv for the scaled epilogue)
    gemm1_tf32_kernel<<<(N_NODES + 127) / 128, 256>>>(x, W1);

    // CSR build (excl self-loops)
    scan1_kernel<<<NB_SCAN, SCAN_BLOCK>>>();
    scan2_kernel<<<1, SCAN_BLOCK>>>();
    scan3_kernel<<<(N_NODES + 1 + 255) / 256, 256>>>();
    fill_edges_kernel<<<(N_EDGES + 255) / 256, 256>>>(src, dst);

    // fused aggregate + layer-2 transform
    agg1_fused_kernel<<<(N_NODES * 32 + 255) / 256, 256>>>(b1, W2);

    // layer-2 aggregate
    agg2_csr_kernel<<<(N_NODES * 32 + 255) / 256, 256>>>(b2, out);
}

// round 9
// speedup vs baseline: 2.4562x; 1.1159x over previous
#include <cuda_runtime.h>
#include <cuda_fp16.h>
#include <mma.h>
#include <cstdint>

using namespace nvcuda;

#define N_NODES 100000
#define N_EDGES 1600000
#define IN_DIM  165
#define HIDDEN  128
#define OUT_DIM 2

#define XPITCH 192            // fp16 X row pitch (384 B, 16B-aligned, covers K=165)
#define KSTEP  32
#define NITER  6              // 192 / 32

#define SCAN_BLOCK 512
#define NB_SCAN ((N_NODES + SCAN_BLOCK - 1) / SCAN_BLOCK)   // 196

// ---------------------------------------------------------------------------
// Static scratch
// ---------------------------------------------------------------------------
__device__ __align__(16) __half g_xh[(size_t)N_NODES * XPITCH];   // fp16 X, padded
__device__ __align__(16) __half g_w1h[XPITCH * HIDDEN];           // fp16 W1, padded rows
__device__ __align__(16) __half g_h1h[(size_t)N_NODES * HIDDEN];  // dinv-scaled fp16 h1
__device__ float g_h2s[(size_t)N_NODES * OUT_DIM];                // dinv-scaled h2
__device__ float g_dinv[N_NODES];
__device__ int   g_cnt[N_NODES];
__device__ int   g_rowstart[N_NODES + 1];
__device__ int   g_cursor[N_NODES];
__device__ int   g_bsum[NB_SCAN];
__device__ int   g_bsum_ex[NB_SCAN];
__device__ int   g_csr_src[N_EDGES];

__device__ __forceinline__ void cp_async16(void* smem_dst, const void* gmem_src,
                                           int src_bytes) {
    uint32_t s = (uint32_t)__cvta_generic_to_shared(smem_dst);
    asm volatile("cp.async.cg.shared.global [%0], [%1], 16, %2;"
                 :: "r"(s), "l"(gmem_src), "r"(src_bytes));
}

// ---------------------------------------------------------------------------
// fp16 conversion pre-pass (round-to-nearest; zero pad beyond IN_DIM)
// ---------------------------------------------------------------------------
__global__ void convert_x_kernel(const float* __restrict__ X) {
    int i = blockIdx.x * blockDim.x + threadIdx.x;       // one __half2 each
    if (i >= N_NODES * (XPITCH / 2)) return;
    int r  = i / (XPITCH / 2);
    int c2 = i % (XPITCH / 2);
    int c  = c2 * 2;
    float a = (c     < IN_DIM) ? X[(size_t)r * IN_DIM + c]     : 0.f;
    float b = (c + 1 < IN_DIM) ? X[(size_t)r * IN_DIM + c + 1] : 0.f;
    ((__half2*)g_xh)[(size_t)r * (XPITCH / 2) + c2] = __floats2half2_rn(a, b);
}

__global__ void convert_w_kernel(const float* __restrict__ W) {
    int i = blockIdx.x * blockDim.x + threadIdx.x;       // one __half2 each
    if (i >= XPITCH * (HIDDEN / 2)) return;
    int r  = i / (HIDDEN / 2);
    int c2 = i % (HIDDEN / 2);
    int c  = c2 * 2;
    float a = (r < IN_DIM) ? W[(size_t)r * HIDDEN + c]     : 0.f;
    float b = (r < IN_DIM) ? W[(size_t)r * HIDDEN + c + 1] : 0.f;
    ((__half2*)g_w1h)[i] = __floats2half2_rn(a, b);
}

// ---------------------------------------------------------------------------
// degree / CSR build (counting sort by dst; self-loops handled in epilogues)
// ---------------------------------------------------------------------------
__global__ void zero_cnt_kernel() {
    int i = blockIdx.x * blockDim.x + threadIdx.x;
    if (i < N_NODES) g_cnt[i] = 0;
}

__global__ void hist_kernel(const int* __restrict__ dst) {
    int e = blockIdx.x * blockDim.x + threadIdx.x;
    if (e < N_EDGES) atomicAdd(&g_cnt[dst[e]], 1);
}

__global__ void dinv_kernel() {
    int i = blockIdx.x * blockDim.x + threadIdx.x;
    if (i < N_NODES) g_dinv[i] = rsqrtf((float)(g_cnt[i] + 1));  // +1 = self-loop
}

__global__ void scan1_kernel() {
    __shared__ int s0[SCAN_BLOCK], s1[SCAN_BLOCK];
    int t = threadIdx.x;
    int i = blockIdx.x * SCAN_BLOCK + t;
    int v = (i < N_NODES) ? g_cnt[i] : 0;
    int* a = s0; int* b = s1;
    a[t] = v;
    __syncthreads();
#pragma unroll
    for (int off = 1; off < SCAN_BLOCK; off <<= 1) {
        b[t] = (t >= off) ? a[t] + a[t - off] : a[t];
        __syncthreads();
        int* tmp = a; a = b; b = tmp;
    }
    if (i < N_NODES) g_rowstart[i] = a[t] - v;
    if (t == SCAN_BLOCK - 1) g_bsum[blockIdx.x] = a[t];
}

__global__ void scan2_kernel() {
    __shared__ int s0[SCAN_BLOCK], s1[SCAN_BLOCK];
    int t = threadIdx.x;
    int v = (t < NB_SCAN) ? g_bsum[t] : 0;
    int* a = s0; int* b = s1;
    a[t] = v;
    __syncthreads();
#pragma unroll
    for (int off = 1; off < SCAN_BLOCK; off <<= 1) {
        b[t] = (t >= off) ? a[t] + a[t - off] : a[t];
        __syncthreads();
        int* tmp = a; a = b; b = tmp;
    }
    if (t < NB_SCAN) g_bsum_ex[t] = a[t] - v;
}

__global__ void scan3_kernel() {
    int i = blockIdx.x * blockDim.x + threadIdx.x;
    if (i < N_NODES) {
        int r = g_rowstart[i] + g_bsum_ex[i / SCAN_BLOCK];
        g_rowstart[i] = r;
        g_cursor[i]   = r;
    } else if (i == N_NODES) {
        g_rowstart[N_NODES] = N_EDGES;
    }
}

__global__ void fill_edges_kernel(const int* __restrict__ src,
                                  const int* __restrict__ dst) {
    int e = blockIdx.x * blockDim.x + threadIdx.x;
    if (e < N_EDGES) {
        int d   = dst[e];
        int pos = atomicAdd(&g_cursor[d], 1);
        g_csr_src[pos] = src[e];
    }
}

// ---------------------------------------------------------------------------
// GEMM1 (fp16 wmma m16n16k16, double-buffered cp.async):
// h1h[r,:] = dinv[r] * (x[r,:] @ W1)   fp32 accum, stored fp16
// block tile 128x128, 8 warps (4M x 2N), k-step 32, 6 iters
// smem: As 2x128x40h (20480B) | Bs 2x32x136h (17408B); stage overlays As
// ---------------------------------------------------------------------------
__global__ void gemm1_fp16_kernel() {
    __shared__ __align__(16) unsigned char sraw[20480 + 17408];
    __half (*As)[128][40] = reinterpret_cast<__half(*)[128][40]>(sraw);
    __half (*Bs)[32][136] = reinterpret_cast<__half(*)[32][136]>(sraw + 20480);
    float  (*stage)[16][20] = reinterpret_cast<float(*)[16][20]>(sraw);  // post-mainloop

    const int tid    = threadIdx.x;
    const int wid    = tid >> 5;
    const int lane   = tid & 31;
    const int warp_m = wid & 3;
    const int warp_n = wid >> 2;
    const int row0   = blockIdx.x * 128;

    // A: 128 rows x 4 chunks(8h=16B); B: 32 rows x 16 chunks — 512 tasks each
    auto load_tiles = [&](int buf, int k0) {
#pragma unroll
        for (int t = 0; t < 2; t++) {
            int idx = tid + t * 256;
            int r = idx >> 2, ch = idx & 3;
            int gr = row0 + r;
            int nb = (gr < N_NODES) ? 16 : 0;
            cp_async16(&As[buf][r][ch * 8],
                       g_xh + (size_t)gr * XPITCH + k0 + ch * 8, nb);
        }
#pragma unroll
        for (int t = 0; t < 2; t++) {
            int idx = tid + t * 256;
            int r = idx >> 4, ch = idx & 15;
            cp_async16(&Bs[buf][r][ch * 8],
                       g_w1h + (size_t)(k0 + r) * HIDDEN + ch * 8, 16);
        }
    };

    wmma::fragment<wmma::accumulator, 16, 16, 16, float> acc[2][4];
#pragma unroll
    for (int i = 0; i < 2; i++)
#pragma unroll
        for (int j = 0; j < 4; j++) wmma::fill_fragment(acc[i][j], 0.f);

    load_tiles(0, 0);
    asm volatile("cp.async.commit_group;");

    for (int it = 0; it < NITER; it++) {
        if (it + 1 < NITER) {
            load_tiles((it + 1) & 1, (it + 1) * KSTEP);
            asm volatile("cp.async.commit_group;");
            asm volatile("cp.async.wait_group 1;");
        } else {
            asm volatile("cp.async.wait_group 0;");
        }
        __syncthreads();

        int buf = it & 1;
        wmma::fragment<wmma::matrix_a, 16, 16, 16, __half, wmma::row_major> af[2];
        wmma::fragment<wmma::matrix_b, 16, 16, 16, __half, wmma::row_major> bf[4];
#pragma unroll
        for (int kk = 0; kk < KSTEP; kk += 16) {
#pragma unroll
            for (int i = 0; i < 2; i++)
                wmma::load_matrix_sync(af[i], &As[buf][warp_m * 32 + i * 16][kk], 40);
#pragma unroll
            for (int j = 0; j < 4; j++)
                wmma::load_matrix_sync(bf[j], &Bs[buf][kk][warp_n * 64 + j * 16], 136);
#pragma unroll
            for (int i = 0; i < 2; i++)
#pragma unroll
                for (int j = 0; j < 4; j++)
                    wmma::mma_sync(acc[i][j], af[i], bf[j], acc[i][j]);
        }
        __syncthreads();
    }

    // epilogue: stage each 16x16 tile (overlays As), scale by dinv, store fp16
#pragma unroll
    for (int i = 0; i < 2; i++) {
#pragma unroll
        for (int j = 0; j < 4; j++) {
            wmma::store_matrix_sync(&stage[wid][0][0], acc[i][j], 20, wmma::mem_row_major);
            __syncwarp();
            int r = row0 + warp_m * 32 + i * 16 + (lane >> 1);
            int c = warp_n * 64 + j * 16 + (lane & 1) * 8;
            if (r < N_NODES) {
                float di = g_dinv[r];
                const float* sp = &stage[wid][lane >> 1][(lane & 1) * 8];
                __half2 p0 = __floats2half2_rn(sp[0] * di, sp[1] * di);
                __half2 p1 = __floats2half2_rn(sp[2] * di, sp[3] * di);
                __half2 p2 = __floats2half2_rn(sp[4] * di, sp[5] * di);
                __half2 p3 = __floats2half2_rn(sp[6] * di, sp[7] * di);
                uint4 pk;
                pk.x = *(const uint32_t*)&p0;
                pk.y = *(const uint32_t*)&p1;
                pk.z = *(const uint32_t*)&p2;
                pk.w = *(const uint32_t*)&p3;
                *(uint4*)&g_h1h[(size_t)r * HIDDEN + c] = pk;
            }
            __syncwarp();
        }
    }
}

// ---------------------------------------------------------------------------
// agg1 + layer2 fused (CSR): one warp per node, lane owns feats 4L..4L+3.
// ---------------------------------------------------------------------------
__global__ void agg1_fused_kernel(const float* __restrict__ b1,
                                  const float* __restrict__ W2) {
    int warp = (blockIdx.x * blockDim.x + threadIdx.x) >> 5;
    int lane = threadIdx.x & 31;
    if (warp >= N_NODES) return;
    int node  = warp;
    int start = g_rowstart[node];
    int end   = g_rowstart[node + 1];

    float4 acc;
    {   // self-loop term
        uint2 v = ((const uint2*)(g_h1h + (size_t)node * HIDDEN))[lane];
        float2 f0 = __half22float2(*reinterpret_cast<__half2*>(&v.x));
        float2 f1 = __half22float2(*reinterpret_cast<__half2*>(&v.y));
        acc = make_float4(f0.x, f0.y, f1.x, f1.y);
    }

    for (int base = start; base < end; base += 32) {
        int idx = base + lane;
        int s_l = (idx < end) ? g_csr_src[idx] : 0;
        int m = min(32, end - base);
        int j = 0;
        for (; j + 8 <= m; j += 8) {
            uint2 v[8];
#pragma unroll
            for (int u = 0; u < 8; u++) {
                int s = __shfl_sync(0xffffffffu, s_l, j + u);
                v[u] = ((const uint2*)(g_h1h + (size_t)s * HIDDEN))[lane];
            }
#pragma unroll
            for (int u = 0; u < 8; u++) {
                float2 f0 = __half22float2(*reinterpret_cast<__half2*>(&v[u].x));
                float2 f1 = __half22float2(*reinterpret_cast<__half2*>(&v[u].y));
                acc.x += f0.x; acc.y += f0.y; acc.z += f1.x; acc.w += f1.y;
            }
        }
        for (; j + 4 <= m; j += 4) {
            uint2 v[4];
#pragma unroll
            for (int u = 0; u < 4; u++) {
                int s = __shfl_sync(0xffffffffu, s_l, j + u);
                v[u] = ((const uint2*)(g_h1h + (size_t)s * HIDDEN))[lane];
            }
#pragma unroll
            for (int u = 0; u < 4; u++) {
                float2 f0 = __half22float2(*reinterpret_cast<__half2*>(&v[u].x));
                float2 f1 = __half22float2(*reinterpret_cast<__half2*>(&v[u].y));
                acc.x += f0.x; acc.y += f0.y; acc.z += f1.x; acc.w += f1.y;
            }
        }
        for (; j < m; j++) {
            int s = __shfl_sync(0xffffffffu, s_l, j);
            uint2 v = ((const uint2*)(g_h1h + (size_t)s * HIDDEN))[lane];
            float2 f0 = __half22float2(*reinterpret_cast<__half2*>(&v.x));
            float2 f1 = __half22float2(*reinterpret_cast<__half2*>(&v.y));
            acc.x += f0.x; acc.y += f0.y; acc.z += f1.x; acc.w += f1.y;
        }
    }

    float dd = g_dinv[node];
    float4 bb = ((const float4*)b1)[lane];
    float h0 = fmaxf(fmaf(dd, acc.x, bb.x), 0.f);
    float h1v = fmaxf(fmaf(dd, acc.y, bb.y), 0.f);
    float h2v = fmaxf(fmaf(dd, acc.z, bb.z), 0.f);
    float h3 = fmaxf(fmaf(dd, acc.w, bb.w), 0.f);
    const float4* wv = (const float4*)W2;   // [128][2] row-major
    float4 wa = wv[2 * lane], wb = wv[2 * lane + 1];
    float o0 = h0 * wa.x + h1v * wa.z + h2v * wb.x + h3 * wb.z;
    float o1 = h0 * wa.y + h1v * wa.w + h2v * wb.y + h3 * wb.w;
#pragma unroll
    for (int off = 16; off; off >>= 1) {
        o0 += __shfl_xor_sync(0xffffffffu, o0, off);
        o1 += __shfl_xor_sync(0xffffffffu, o1, off);
    }
    if (lane == 0) {
        g_h2s[2 * node]     = dd * o0;   // pre-scaled for layer-2 aggregation
        g_h2s[2 * node + 1] = dd * o1;
    }
}

// ---------------------------------------------------------------------------
// agg2 (CSR): one warp per node; out[d] = dinv[d]*(h2s[d] + sum h2s[s]) + b2
// ---------------------------------------------------------------------------
__global__ void agg2_csr_kernel(const float* __restrict__ b2,
                                float* __restrict__ out) {
    int warp = (blockIdx.x * blockDim.x + threadIdx.x) >> 5;
    int lane = threadIdx.x & 31;
    if (warp >= N_NODES) return;
    int node  = warp;
    int start = g_rowstart[node];
    int end   = g_rowstart[node + 1];

    float a0 = 0.f, a1 = 0.f;
    for (int idx = start + lane; idx < end; idx += 32) {
        int s    = g_csr_src[idx];
        float2 h = *(const float2*)(g_h2s + 2 * (size_t)s);
        a0 += h.x;
        a1 += h.y;
    }
#pragma unroll
    for (int off = 16; off; off >>= 1) {
        a0 += __shfl_xor_sync(0xffffffffu, a0, off);
        a1 += __shfl_xor_sync(0xffffffffu, a1, off);
    }
    if (lane == 0) {
        float2 hs = *(const float2*)(g_h2s + 2 * (size_t)node);  // self-loop
        float dd  = g_dinv[node];
        out[2 * node]     = fmaf(dd, a0 + hs.x, b2[0]);
        out[2 * node + 1] = fmaf(dd, a1 + hs.y, b2[1]);
    }
}

// ---------------------------------------------------------------------------
extern "C" void kernel_launch(void* const* d_in, const int* in_sizes, int n_in,
                              void* d_out, int out_size) {
    const float* x  = (const float*)d_in[0];
    const int*   ei = (const int*)d_in[1];
    const float* W1 = (const float*)d_in[2];
    const float* b1 = (const float*)d_in[3];
    const float* W2 = (const float*)d_in[4];
    const float* b2 = (const float*)d_in[5];
    float*       out = (float*)d_out;

    const int* src = ei;
    const int* dst = ei + N_EDGES;

    // fp16 conversions (independent of graph work)
    convert_x_kernel<<<(N_NODES * (XPITCH / 2) + 255) / 256, 256>>>(x);
    convert_w_kernel<<<(XPITCH * (HIDDEN / 2) + 255) / 256, 256>>>(W1);

    // degree / dinv
    zero_cnt_kernel<<<(N_NODES + 255) / 256, 256>>>();
    hist_kernel<<<(N_EDGES + 255) / 256, 256>>>(dst);
    dinv_kernel<<<(N_NODES + 255) / 256, 256>>>();

    // GEMM (needs dinv for the scaled epilogue)
    gemm1_fp16_kernel<<<(N_NODES + 127) / 128, 256>>>();

    // CSR build (excl self-loops)
    scan1_kernel<<<NB_SCAN, SCAN_BLOCK>>>();
    scan2_kernel<<<1, SCAN_BLOCK>>>();
    scan3_kernel<<<(N_NODES + 1 + 255) / 256, 256>>>();
    fill_edges_kernel<<<(N_EDGES + 255) / 256, 256>>>(src, dst);

    // fused aggregate + layer-2 transform
    agg1_fused_kernel<<<(N_NODES * 32 + 255) / 256, 256>>>(b1, W2);

    // layer-2 aggregate
    agg2_csr_kernel<<<(N_NODES * 32 + 255) / 256, 256>>>(b2, out);
}

// round 10
// speedup vs baseline: 2.6672x; 1.0859x over previous
#include <cuda_runtime.h>
#include <cuda_fp16.h>
#include <mma.h>
#include <cstdint>

using namespace nvcuda;

#define N_NODES 100000
#define N_EDGES 1600000
#define IN_DIM  165
#define HIDDEN  128
#define OUT_DIM 2

#define XPITCH 192            // fp16 X row pitch (384 B, 16B-aligned, covers K=165)
#define KSTEP  32
#define NITER  6              // 192 / 32

#define SCAN_BLOCK 512
#define NB_SCAN ((N_NODES + SCAN_BLOCK - 1) / SCAN_BLOCK)   // 196

// ---------------------------------------------------------------------------
// Static scratch
// ---------------------------------------------------------------------------
__device__ __align__(16) __half g_xh[(size_t)N_NODES * XPITCH];   // fp16 X, padded
__device__ __align__(16) __half g_w1h[XPITCH * HIDDEN];           // fp16 W1, padded rows
__device__ __align__(16) __half g_h1h[(size_t)N_NODES * HIDDEN];  // dinv-scaled fp16 h1
__device__ float g_h2s[(size_t)N_NODES * OUT_DIM];                // dinv-scaled h2
__device__ float g_dinv[N_NODES];
__device__ int   g_cnt[N_NODES];
__device__ int   g_rowstart[N_NODES + 1];
__device__ int   g_cursor[N_NODES];
__device__ int   g_bsum[NB_SCAN];
__device__ int   g_bsum_ex[NB_SCAN];
__device__ int   g_csr_src[N_EDGES];

__device__ __forceinline__ void cp_async16(void* smem_dst, const void* gmem_src,
                                           int src_bytes) {
    uint32_t s = (uint32_t)__cvta_generic_to_shared(smem_dst);
    asm volatile("cp.async.cg.shared.global [%0], [%1], 16, %2;"
                 :: "r"(s), "l"(gmem_src), "r"(src_bytes));
}

// ---------------------------------------------------------------------------
// fp16 conversion pre-pass (round-to-nearest; zero pad beyond IN_DIM)
// ---------------------------------------------------------------------------
__global__ void convert_x_kernel(const float* __restrict__ X) {
    int i = blockIdx.x * blockDim.x + threadIdx.x;       // one __half2 each
    if (i >= N_NODES * (XPITCH / 2)) return;
    int r  = i / (XPITCH / 2);
    int c2 = i % (XPITCH / 2);
    int c  = c2 * 2;
    float a = (c     < IN_DIM) ? X[(size_t)r * IN_DIM + c]     : 0.f;
    float b = (c + 1 < IN_DIM) ? X[(size_t)r * IN_DIM + c + 1] : 0.f;
    ((__half2*)g_xh)[(size_t)r * (XPITCH / 2) + c2] = __floats2half2_rn(a, b);
}

__global__ void convert_w_kernel(const float* __restrict__ W) {
    int i = blockIdx.x * blockDim.x + threadIdx.x;       // one __half2 each
    if (i >= XPITCH * (HIDDEN / 2)) return;
    int r  = i / (HIDDEN / 2);
    int c2 = i % (HIDDEN / 2);
    int c  = c2 * 2;
    float a = (r < IN_DIM) ? W[(size_t)r * HIDDEN + c]     : 0.f;
    float b = (r < IN_DIM) ? W[(size_t)r * HIDDEN + c + 1] : 0.f;
    ((__half2*)g_w1h)[i] = __floats2half2_rn(a, b);
}

// ---------------------------------------------------------------------------
// degree / CSR build (counting sort by dst; self-loops handled in epilogues)
// ---------------------------------------------------------------------------
__global__ void zero_cnt_kernel() {
    int i = blockIdx.x * blockDim.x + threadIdx.x;
    if (i < N_NODES) g_cnt[i] = 0;
}

// 4 edges per thread via int4 (dst is 16B-aligned: N_EDGES*4B is 16B multiple)
__global__ void hist_kernel(const int* __restrict__ dst) {
    int i = blockIdx.x * blockDim.x + threadIdx.x;
    if (i >= N_EDGES / 4) return;
    int4 d = ((const int4*)dst)[i];
    atomicAdd(&g_cnt[d.x], 1);
    atomicAdd(&g_cnt[d.y], 1);
    atomicAdd(&g_cnt[d.z], 1);
    atomicAdd(&g_cnt[d.w], 1);
}

__global__ void dinv_kernel() {
    int i = blockIdx.x * blockDim.x + threadIdx.x;
    if (i < N_NODES) g_dinv[i] = rsqrtf((float)(g_cnt[i] + 1));  // +1 = self-loop
}

__global__ void scan1_kernel() {
    __shared__ int s0[SCAN_BLOCK], s1[SCAN_BLOCK];
    int t = threadIdx.x;
    int i = blockIdx.x * SCAN_BLOCK + t;
    int v = (i < N_NODES) ? g_cnt[i] : 0;
    int* a = s0; int* b = s1;
    a[t] = v;
    __syncthreads();
#pragma unroll
    for (int off = 1; off < SCAN_BLOCK; off <<= 1) {
        b[t] = (t >= off) ? a[t] + a[t - off] : a[t];
        __syncthreads();
        int* tmp = a; a = b; b = tmp;
    }
    if (i < N_NODES) g_rowstart[i] = a[t] - v;
    if (t == SCAN_BLOCK - 1) g_bsum[blockIdx.x] = a[t];
}

__global__ void scan2_kernel() {
    __shared__ int s0[SCAN_BLOCK], s1[SCAN_BLOCK];
    int t = threadIdx.x;
    int v = (t < NB_SCAN) ? g_bsum[t] : 0;
    int* a = s0; int* b = s1;
    a[t] = v;
    __syncthreads();
#pragma unroll
    for (int off = 1; off < SCAN_BLOCK; off <<= 1) {
        b[t] = (t >= off) ? a[t] + a[t - off] : a[t];
        __syncthreads();
        int* tmp = a; a = b; b = tmp;
    }
    if (t < NB_SCAN) g_bsum_ex[t] = a[t] - v;
}

__global__ void scan3_kernel() {
    int i = blockIdx.x * blockDim.x + threadIdx.x;
    if (i < N_NODES) {
        int r = g_rowstart[i] + g_bsum_ex[i / SCAN_BLOCK];
        g_rowstart[i] = r;
        g_cursor[i]   = r;
    } else if (i == N_NODES) {
        g_rowstart[N_NODES] = N_EDGES;
    }
}

__global__ void fill_edges_kernel(const int* __restrict__ src,
                                  const int* __restrict__ dst) {
    int e = blockIdx.x * blockDim.x + threadIdx.x;
    if (e < N_EDGES) {
        int d   = dst[e];
        int pos = atomicAdd(&g_cursor[d], 1);
        g_csr_src[pos] = src[e];
    }
}

// ---------------------------------------------------------------------------
// GEMM1 (fp16 wmma m16n16k16, double-buffered cp.async):
// h1h[r,:] = dinv[r] * (x[r,:] @ W1)   fp32 accum, stored fp16
// ---------------------------------------------------------------------------
__global__ void gemm1_fp16_kernel() {
    __shared__ __align__(16) unsigned char sraw[20480 + 17408];
    __half (*As)[128][40] = reinterpret_cast<__half(*)[128][40]>(sraw);
    __half (*Bs)[32][136] = reinterpret_cast<__half(*)[32][136]>(sraw + 20480);
    float  (*stage)[16][20] = reinterpret_cast<float(*)[16][20]>(sraw);  // post-mainloop

    const int tid    = threadIdx.x;
    const int wid    = tid >> 5;
    const int lane   = tid & 31;
    const int warp_m = wid & 3;
    const int warp_n = wid >> 2;
    const int row0   = blockIdx.x * 128;

    auto load_tiles = [&](int buf, int k0) {
#pragma unroll
        for (int t = 0; t < 2; t++) {
            int idx = tid + t * 256;
            int r = idx >> 2, ch = idx & 3;
            int gr = row0 + r;
            int nb = (gr < N_NODES) ? 16 : 0;
            cp_async16(&As[buf][r][ch * 8],
                       g_xh + (size_t)gr * XPITCH + k0 + ch * 8, nb);
        }
#pragma unroll
        for (int t = 0; t < 2; t++) {
            int idx = tid + t * 256;
            int r = idx >> 4, ch = idx & 15;
            cp_async16(&Bs[buf][r][ch * 8],
                       g_w1h + (size_t)(k0 + r) * HIDDEN + ch * 8, 16);
        }
    };

    wmma::fragment<wmma::accumulator, 16, 16, 16, float> acc[2][4];
#pragma unroll
    for (int i = 0; i < 2; i++)
#pragma unroll
        for (int j = 0; j < 4; j++) wmma::fill_fragment(acc[i][j], 0.f);

    load_tiles(0, 0);
    asm volatile("cp.async.commit_group;");

    for (int it = 0; it < NITER; it++) {
        if (it + 1 < NITER) {
            load_tiles((it + 1) & 1, (it + 1) * KSTEP);
            asm volatile("cp.async.commit_group;");
            asm volatile("cp.async.wait_group 1;");
        } else {
            asm volatile("cp.async.wait_group 0;");
        }
        __syncthreads();

        int buf = it & 1;
        wmma::fragment<wmma::matrix_a, 16, 16, 16, __half, wmma::row_major> af[2];
        wmma::fragment<wmma::matrix_b, 16, 16, 16, __half, wmma::row_major> bf[4];
#pragma unroll
        for (int kk = 0; kk < KSTEP; kk += 16) {
#pragma unroll
            for (int i = 0; i < 2; i++)
                wmma::load_matrix_sync(af[i], &As[buf][warp_m * 32 + i * 16][kk], 40);
#pragma unroll
            for (int j = 0; j < 4; j++)
                wmma::load_matrix_sync(bf[j], &Bs[buf][kk][warp_n * 64 + j * 16], 136);
#pragma unroll
            for (int i = 0; i < 2; i++)
#pragma unroll
                for (int j = 0; j < 4; j++)
                    wmma::mma_sync(acc[i][j], af[i], bf[j], acc[i][j]);
        }
        __syncthreads();
    }

#pragma unroll
    for (int i = 0; i < 2; i++) {
#pragma unroll
        for (int j = 0; j < 4; j++) {
            wmma::store_matrix_sync(&stage[wid][0][0], acc[i][j], 20, wmma::mem_row_major);
            __syncwarp();
            int r = row0 + warp_m * 32 + i * 16 + (lane >> 1);
            int c = warp_n * 64 + j * 16 + (lane & 1) * 8;
            if (r < N_NODES) {
                float di = g_dinv[r];
                const float* sp = &stage[wid][lane >> 1][(lane & 1) * 8];
                __half2 p0 = __floats2half2_rn(sp[0] * di, sp[1] * di);
                __half2 p1 = __floats2half2_rn(sp[2] * di, sp[3] * di);
                __half2 p2 = __floats2half2_rn(sp[4] * di, sp[5] * di);
                __half2 p3 = __floats2half2_rn(sp[6] * di, sp[7] * di);
                uint4 pk;
                pk.x = *(const uint32_t*)&p0;
                pk.y = *(const uint32_t*)&p1;
                pk.z = *(const uint32_t*)&p2;
                pk.w = *(const uint32_t*)&p3;
                *(uint4*)&g_h1h[(size_t)r * HIDDEN + c] = pk;
            }
            __syncwarp();
        }
    }
}

// ---------------------------------------------------------------------------
// agg1 + layer2 fused (CSR): one warp per node, lane owns feats 4L..4L+3.
// ---------------------------------------------------------------------------
__global__ void agg1_fused_kernel(const float* __restrict__ b1,
                                  const float* __restrict__ W2) {
    int warp = (blockIdx.x * blockDim.x + threadIdx.x) >> 5;
    int lane = threadIdx.x & 31;
    if (warp >= N_NODES) return;
    int node  = warp;
    int start = g_rowstart[node];
    int end   = g_rowstart[node + 1];

    float4 acc;
    {   // self-loop term
        uint2 v = ((const uint2*)(g_h1h + (size_t)node * HIDDEN))[lane];
        float2 f0 = __half22float2(*reinterpret_cast<__half2*>(&v.x));
        float2 f1 = __half22float2(*reinterpret_cast<__half2*>(&v.y));
        acc = make_float4(f0.x, f0.y, f1.x, f1.y);
    }

    for (int base = start; base < end; base += 32) {
        int idx = base + lane;
        int s_l = (idx < end) ? g_csr_src[idx] : 0;
        int m = min(32, end - base);
        int j = 0;
        for (; j + 8 <= m; j += 8) {
            uint2 v[8];
#pragma unroll
            for (int u = 0; u < 8; u++) {
                int s = __shfl_sync(0xffffffffu, s_l, j + u);
                v[u] = ((const uint2*)(g_h1h + (size_t)s * HIDDEN))[lane];
            }
#pragma unroll
            for (int u = 0; u < 8; u++) {
                float2 f0 = __half22float2(*reinterpret_cast<__half2*>(&v[u].x));
                float2 f1 = __half22float2(*reinterpret_cast<__half2*>(&v[u].y));
                acc.x += f0.x; acc.y += f0.y; acc.z += f1.x; acc.w += f1.y;
            }
        }
        for (; j + 4 <= m; j += 4) {
            uint2 v[4];
#pragma unroll
            for (int u = 0; u < 4; u++) {
                int s = __shfl_sync(0xffffffffu, s_l, j + u);
                v[u] = ((const uint2*)(g_h1h + (size_t)s * HIDDEN))[lane];
            }
#pragma unroll
            for (int u = 0; u < 4; u++) {
                float2 f0 = __half22float2(*reinterpret_cast<__half2*>(&v[u].x));
                float2 f1 = __half22float2(*reinterpret_cast<__half2*>(&v[u].y));
                acc.x += f0.x; acc.y += f0.y; acc.z += f1.x; acc.w += f1.y;
            }
        }
        for (; j < m; j++) {
            int s = __shfl_sync(0xffffffffu, s_l, j);
            uint2 v = ((const uint2*)(g_h1h + (size_t)s * HIDDEN))[lane];
            float2 f0 = __half22float2(*reinterpret_cast<__half2*>(&v.x));
            float2 f1 = __half22float2(*reinterpret_cast<__half2*>(&v.y));
            acc.x += f0.x; acc.y += f0.y; acc.z += f1.x; acc.w += f1.y;
        }
    }

    float dd = g_dinv[node];
    float4 bb = ((const float4*)b1)[lane];
    float h0 = fmaxf(fmaf(dd, acc.x, bb.x), 0.f);
    float h1v = fmaxf(fmaf(dd, acc.y, bb.y), 0.f);
    float h2v = fmaxf(fmaf(dd, acc.z, bb.z), 0.f);
    float h3 = fmaxf(fmaf(dd, acc.w, bb.w), 0.f);
    const float4* wv = (const float4*)W2;   // [128][2] row-major
    float4 wa = wv[2 * lane], wb = wv[2 * lane + 1];
    float o0 = h0 * wa.x + h1v * wa.z + h2v * wb.x + h3 * wb.z;
    float o1 = h0 * wa.y + h1v * wa.w + h2v * wb.y + h3 * wb.w;
#pragma unroll
    for (int off = 16; off; off >>= 1) {
        o0 += __shfl_xor_sync(0xffffffffu, o0, off);
        o1 += __shfl_xor_sync(0xffffffffu, o1, off);
    }
    if (lane == 0) {
        g_h2s[2 * node]     = dd * o0;   // pre-scaled for layer-2 aggregation
        g_h2s[2 * node + 1] = dd * o1;
    }
}

// ---------------------------------------------------------------------------
// agg2 (CSR): one warp per node; out[d] = dinv[d]*(h2s[d] + sum h2s[s]) + b2
// ---------------------------------------------------------------------------
__global__ void agg2_csr_kernel(const float* __restrict__ b2,
                                float* __restrict__ out) {
    int warp = (blockIdx.x * blockDim.x + threadIdx.x) >> 5;
    int lane = threadIdx.x & 31;
    if (warp >= N_NODES) return;
    int node  = warp;
    int start = g_rowstart[node];
    int end   = g_rowstart[node + 1];

    float a0 = 0.f, a1 = 0.f;
    for (int idx = start + lane; idx < end; idx += 32) {
        int s    = g_csr_src[idx];
        float2 h = *(const float2*)(g_h2s + 2 * (size_t)s);
        a0 += h.x;
        a1 += h.y;
    }
#pragma unroll
    for (int off = 16; off; off >>= 1) {
        a0 += __shfl_xor_sync(0xffffffffu, a0, off);
        a1 += __shfl_xor_sync(0xffffffffu, a1, off);
    }
    if (lane == 0) {
        float2 hs = *(const float2*)(g_h2s + 2 * (size_t)node);  // self-loop
        float dd  = g_dinv[node];
        out[2 * node]     = fmaf(dd, a0 + hs.x, b2[0]);
        out[2 * node + 1] = fmaf(dd, a1 + hs.y, b2[1]);
    }
}

// ---------------------------------------------------------------------------
extern "C" void kernel_launch(void* const* d_in, const int* in_sizes, int n_in,
                              void* d_out, int out_size) {
    const float* x  = (const float*)d_in[0];
    const int*   ei = (const int*)d_in[1];
    const float* W1 = (const float*)d_in[2];
    const float* b1 = (const float*)d_in[3];
    const float* W2 = (const float*)d_in[4];
    const float* b2 = (const float*)d_in[5];
    float*       out = (float*)d_out;

    const int* src = ei;
    const int* dst = ei + N_EDGES;

    // persistent side stream + events (created once; no device memory involved)
    static cudaStream_t s2 = nullptr;
    static cudaEvent_t evRoot, evDinv, evFill;
    if (!s2) {
        cudaStreamCreateWithFlags(&s2, cudaStreamNonBlocking);
        cudaEventCreateWithFlags(&evRoot, cudaEventDisableTiming);
        cudaEventCreateWithFlags(&evDinv, cudaEventDisableTiming);
        cudaEventCreateWithFlags(&evFill, cudaEventDisableTiming);
    }

    // fork s2 from the capture-origin stream
    cudaEventRecord(evRoot, 0);
    cudaStreamWaitEvent(s2, evRoot, 0);

    // s2: degree / dinv / CSR build (L2-atomic + scan bound)
    zero_cnt_kernel<<<(N_NODES + 255) / 256, 256, 0, s2>>>();
    hist_kernel<<<(N_EDGES / 4 + 255) / 256, 256, 0, s2>>>(dst);
    dinv_kernel<<<(N_NODES + 255) / 256, 256, 0, s2>>>();
    cudaEventRecord(evDinv, s2);
    scan1_kernel<<<NB_SCAN, SCAN_BLOCK, 0, s2>>>();
    scan2_kernel<<<1, SCAN_BLOCK, 0, s2>>>();
    scan3_kernel<<<(N_NODES + 1 + 255) / 256, 256, 0, s2>>>();
    fill_edges_kernel<<<(N_EDGES + 255) / 256, 256, 0, s2>>>(src, dst);
    cudaEventRecord(evFill, s2);

    // stream 0: fp16 conversions (DRAM-bound) run concurrently with s2
    convert_x_kernel<<<(N_NODES * (XPITCH / 2) + 255) / 256, 256>>>(x);
    convert_w_kernel<<<(XPITCH * (HIDDEN / 2) + 255) / 256, 256>>>(W1);

    // GEMM needs converts (stream 0) + dinv (s2); CSR fill continues under it
    cudaStreamWaitEvent(0, evDinv, 0);
    gemm1_fp16_kernel<<<(N_NODES + 127) / 128, 256>>>();

    // aggregation needs gemm (stream 0) + fill (s2)
    cudaStreamWaitEvent(0, evFill, 0);
    agg1_fused_kernel<<<(N_NODES * 32 + 255) / 256, 256>>>(b1, W2);
    agg2_csr_kernel<<<(N_NODES * 32 + 255) / 256, 256>>>(b2, out);
}